// round 9
// baseline (speedup 1.0000x reference)
#include <cuda_runtime.h>
#include <cuda_bf16.h>
#include <cstdint>
#include <math.h>

#define Bsz   512
#define Nn    256
#define NODES (Bsz * Nn)      // 131072
#define DIN   32
#define HID   128
#define HEADS 4
#define Knn   5
#define DOUT  8
#define CAP   40
#define NEG_SLOPE 0.2f
#define FULLM 0xffffffffu

// ---------------- static device scratch ----------------
__device__ int     g_rdeg[NODES];
__device__ uint8_t g_adj8[(size_t)NODES * CAP];     // local (in-batch) indices
__device__ float   g_hbuf[(size_t)NODES * HID];
__device__ float   g_xbuf[(size_t)NODES * HID];
__device__ float   g_als[(size_t)NODES * HEADS];
__device__ float   g_ald[(size_t)NODES * HEADS];
// bf16 hi/lo images of W^T: [n=128 rows][k] row-major
__device__ __nv_bfloat16 g_w1_hi[128 * DIN],  g_w1_lo[128 * DIN];
__device__ __nv_bfloat16 g_w2_hi[128 * HID],  g_w2_lo[128 * HID];
__device__ __nv_bfloat16 g_wm1_hi[128 * HID], g_wm1_lo[128 * HID];

__device__ __forceinline__ float tanh_fast(float x) {
    return __fdividef(2.f, 1.f + __expf(-2.f * x)) - 1.f;
}
__device__ __forceinline__ float lrelu(float v) {
    return (v > 0.f) ? v : NEG_SLOPE * v;
}
__device__ __forceinline__ uint32_t smem_u32(const void* p) {
    uint32_t a;
    asm("{ .reg .u64 t; cvta.to.shared.u64 t, %1; cvt.u32.u64 %0, t; }" : "=r"(a) : "l"(p));
    return a;
}
__device__ __forceinline__ void ldsm_x4(uint32_t* r, uint32_t addr) {
    asm volatile("ldmatrix.sync.aligned.m8n8.x4.shared.b16 {%0,%1,%2,%3}, [%4];"
                 : "=r"(r[0]), "=r"(r[1]), "=r"(r[2]), "=r"(r[3]) : "r"(addr));
}
__device__ __forceinline__ void ldsm_x2(uint32_t* r, uint32_t addr) {
    asm volatile("ldmatrix.sync.aligned.m8n8.x2.shared.b16 {%0,%1}, [%2];"
                 : "=r"(r[0]), "=r"(r[1]) : "r"(addr));
}
__device__ __forceinline__ void mma_bf16(float* c, const uint32_t* a, const uint32_t* b) {
    asm volatile("mma.sync.aligned.m16n8k16.row.col.f32.bf16.bf16.f32 "
                 "{%0,%1,%2,%3}, {%4,%5,%6,%7}, {%8,%9}, {%0,%1,%2,%3};"
                 : "+f"(c[0]), "+f"(c[1]), "+f"(c[2]), "+f"(c[3])
                 : "r"(a[0]), "r"(a[1]), "r"(a[2]), "r"(a[3]), "r"(b[0]), "r"(b[1]));
}
__device__ __forceinline__ uint32_t pack_bf2(__nv_bfloat16 a, __nv_bfloat16 b) {
    return (uint32_t)__bfloat16_as_ushort(a) | ((uint32_t)__bfloat16_as_ushort(b) << 16);
}

// =====================================================================
// Prep: W [K,128] -> hi/lo bf16 images of W^T [128][K]
// =====================================================================
__global__ void prep_w_kernel(const float* __restrict__ W, int K,
                              __nv_bfloat16* __restrict__ hi, __nv_bfloat16* __restrict__ lo)
{
    int idx = blockIdx.x * blockDim.x + threadIdx.x;
    if (idx >= K * 128) return;
    int k = idx >> 7, n = idx & 127;
    float x = W[idx];
    __nv_bfloat16 h = __float2bfloat16(x);
    __nv_bfloat16 l = __float2bfloat16(x - __bfloat162float(h));
    hi[n * K + k] = h;
    lo[n * K + k] = l;
}

// =====================================================================
// KNN v2: block per batch, 512 threads. Thread (n, half) scans 128
// candidates with early-reject top-5; merge in smem; reverse adjacency
// via smem atomics; output uint8 local indices.
// =====================================================================
__global__ __launch_bounds__(512) void knn_kernel(const float* __restrict__ obs)
{
    __shared__ float   sx[Nn];
    __shared__ float   sy[Nn];
    __shared__ int     sdeg[Nn];
    __shared__ uint8_t sadj[Nn * CAP];          // 10 KB
    __shared__ float   mbd[Nn * 2 * Knn];       // 10 KB
    __shared__ int     mbi[Nn * 2 * Knn];       // 10 KB

    const int b = blockIdx.x;
    const int t = threadIdx.x;
    const int n = t & (Nn - 1);
    const int half = t >> 8;

    if (t < Nn) {
        const size_t base = ((size_t)b * Nn + n) * DIN;
        sx[n] = obs[base + 0];
        sy[n] = obs[base + 1];
        sdeg[n] = 1;
        sadj[n * CAP + 0] = (uint8_t)n;         // self loop first
    }
    __syncthreads();

    const float px = sx[n], py = sy[n];
    float bd[Knn];
    int   bi[Knn];
#pragma unroll
    for (int s = 0; s < Knn; s++) { bd[s] = 3.0e38f; bi[s] = -1; }

    const int j0 = half * 128;
    for (int jj = 0; jj < 128; jj++) {
        const int j = j0 + jj;
        float dx = sx[j] - px;
        float dy = sy[j] - py;
        float d  = fmaf(dx, dx, dy * dy);
        if (j == n) d = 3.0e38f;
        if (d < bd[Knn - 1]) {                  // early reject (~92%)
            bd[Knn - 1] = d; bi[Knn - 1] = j;
#pragma unroll
            for (int s = Knn - 2; s >= 0; s--) {
                if (bd[s + 1] < bd[s]) {
                    float td = bd[s]; bd[s] = bd[s + 1]; bd[s + 1] = td;
                    int   ti = bi[s]; bi[s] = bi[s + 1]; bi[s + 1] = ti;
                }
            }
        }
    }
#pragma unroll
    for (int s = 0; s < Knn; s++) {
        mbd[(n * 2 + half) * Knn + s] = bd[s];
        mbi[(n * 2 + half) * Knn + s] = bi[s];
    }
    __syncthreads();

    if (t < Nn) {
        const float* A  = &mbd[(n * 2 + 0) * Knn];
        const float* B  = &mbd[(n * 2 + 1) * Knn];
        const int*   Ai = &mbi[(n * 2 + 0) * Knn];
        const int*   Bi = &mbi[(n * 2 + 1) * Knn];
        int ia = 0, ib = 0;
#pragma unroll
        for (int s = 0; s < Knn; s++) {
            int jn;
            if (A[ia] <= B[ib]) jn = Ai[ia++];
            else                jn = Bi[ib++];
            int p = atomicAdd(&sdeg[jn], 1);
            if (p < CAP) sadj[jn * CAP + p] = (uint8_t)n;
        }
    }
    __syncthreads();

    if (t < Nn) {
        int deg = min(sdeg[n], CAP);
        g_rdeg[b * Nn + n] = deg;
        uint8_t* dst = g_adj8 + (size_t)(b * Nn + n) * CAP;
        const uint32_t* srcw = (const uint32_t*)&sadj[n * CAP];
#pragma unroll
        for (int w = 0; w < CAP / 4; w++)
            ((uint32_t*)dst)[w] = srcw[w];
    }
}

// =====================================================================
// mma.sync GEMM: 128x128 tile, 8 warps (64x32 warp tiles), split-bf16 x3.
// MODE 0: H = X@W + fused attn-logit dots.  MODE 1: out = tanh(X@Wm1+bm1)@Wm2+bm2.
// =====================================================================
template<int KDIM, int MODE>
__global__ __launch_bounds__(256) void mma_gemm(
    const float* __restrict__ X,
    const __nv_bfloat16* __restrict__ gBhi, const __nv_bfloat16* __restrict__ gBlo,
    const float* __restrict__ asrc, const float* __restrict__ adst,
    const float* __restrict__ bias, const float* __restrict__ Wm2,
    const float* __restrict__ bm2,
    float* __restrict__ H, float* __restrict__ ALS, float* __restrict__ ALD,
    float* __restrict__ OUT)
{
    constexpr int PK = KDIM + 8;
    extern __shared__ __align__(16) char smem[];
    __nv_bfloat16* sAhi = (__nv_bfloat16*)smem;
    __nv_bfloat16* sAlo = sAhi + 128 * PK;
    __nv_bfloat16* sBhi = sAlo + 128 * PK;
    __nv_bfloat16* sBlo = sBhi + 128 * PK;
    float* scr = (float*)(sBlo + 128 * PK);

    const int t = threadIdx.x, wid = t >> 5, lane = t & 31;
    const int r0 = blockIdx.x * 128;

    if (MODE == 0) {
        if (t < 128) { scr[t] = asrc[t]; scr[128 + t] = adst[t]; }
    } else {
        if (t < 128) scr[t] = bias[t];
        for (int e = t; e < 1024; e += 256) scr[128 + e] = Wm2[e];
    }

    for (int idx = t; idx < 128 * (KDIM / 2); idx += 256) {
        int row = idx / (KDIM / 2);
        int k   = (idx % (KDIM / 2)) * 2;
        float2 v = *(const float2*)&X[(size_t)(r0 + row) * KDIM + k];
        __nv_bfloat16 h0 = __float2bfloat16(v.x);
        __nv_bfloat16 h1 = __float2bfloat16(v.y);
        __nv_bfloat16 l0 = __float2bfloat16(v.x - __bfloat162float(h0));
        __nv_bfloat16 l1 = __float2bfloat16(v.y - __bfloat162float(h1));
        *(uint32_t*)&sAhi[row * PK + k] = pack_bf2(h0, h1);
        *(uint32_t*)&sAlo[row * PK + k] = pack_bf2(l0, l1);
    }
    for (int idx = t; idx < 128 * (KDIM / 8); idx += 256) {
        int n  = idx / (KDIM / 8);
        int kc = (idx % (KDIM / 8)) * 8;
        *(float4*)&sBhi[n * PK + kc] = *(const float4*)&gBhi[n * KDIM + kc];
        *(float4*)&sBlo[n * PK + kc] = *(const float4*)&gBlo[n * KDIM + kc];
    }
    __syncthreads();

    const int mbase = (wid & 1) * 64;
    const int nbase = (wid >> 1) * 32;

    float c[4][4][4];
#pragma unroll
    for (int mi = 0; mi < 4; mi++)
#pragma unroll
        for (int ni = 0; ni < 4; ni++)
#pragma unroll
            for (int q = 0; q < 4; q++) c[mi][ni][q] = 0.f;

    const int arow = mbase + (lane & 7) + ((lane >> 3) & 1) * 8;
    const int ak   = (lane >> 4) * 8;
    const int brow = nbase + (lane & 7);
    const int bk   = ((lane >> 3) & 1) * 8;

#pragma unroll
    for (int p = 0; p < 3; p++) {
        const __nv_bfloat16* A  = (p == 2) ? sAlo : sAhi;
        const __nv_bfloat16* Bm = (p == 1) ? sBlo : sBhi;
#pragma unroll
        for (int ks = 0; ks < KDIM / 16; ks++) {
            uint32_t a[4][4], b[4][2];
#pragma unroll
            for (int mi = 0; mi < 4; mi++)
                ldsm_x4(a[mi], smem_u32(&A[(arow + mi * 16) * PK + ks * 16 + ak]));
#pragma unroll
            for (int ni = 0; ni < 4; ni++)
                ldsm_x2(b[ni], smem_u32(&Bm[(brow + ni * 8) * PK + ks * 16 + bk]));
#pragma unroll
            for (int mi = 0; mi < 4; mi++)
#pragma unroll
                for (int ni = 0; ni < 4; ni++)
                    mma_bf16(c[mi][ni], a[mi], b[ni]);
        }
    }
    __syncthreads();

    const int gr = lane >> 2;
    const int qc = (lane & 3) * 2;

    if (MODE == 0) {
        const int head = wid >> 1;
#pragma unroll
        for (int mi = 0; mi < 4; mi++) {
            const int row0 = r0 + mbase + mi * 16 + gr;
            float psA = 0.f, pdA = 0.f, psB = 0.f, pdB = 0.f;
#pragma unroll
            for (int ni = 0; ni < 4; ni++) {
                const int gcol = nbase + ni * 8 + qc;
                float* cc = c[mi][ni];
                *(float2*)&H[(size_t)row0 * HID + gcol] = make_float2(cc[0], cc[1]);
                *(float2*)&H[(size_t)(row0 + 8) * HID + gcol] = make_float2(cc[2], cc[3]);
                psA = fmaf(cc[0], scr[gcol], fmaf(cc[1], scr[gcol + 1], psA));
                pdA = fmaf(cc[0], scr[128 + gcol], fmaf(cc[1], scr[128 + gcol + 1], pdA));
                psB = fmaf(cc[2], scr[gcol], fmaf(cc[3], scr[gcol + 1], psB));
                pdB = fmaf(cc[2], scr[128 + gcol], fmaf(cc[3], scr[128 + gcol + 1], pdB));
            }
            psA += __shfl_xor_sync(FULLM, psA, 1); psA += __shfl_xor_sync(FULLM, psA, 2);
            pdA += __shfl_xor_sync(FULLM, pdA, 1); pdA += __shfl_xor_sync(FULLM, pdA, 2);
            psB += __shfl_xor_sync(FULLM, psB, 1); psB += __shfl_xor_sync(FULLM, psB, 2);
            pdB += __shfl_xor_sync(FULLM, pdB, 1); pdB += __shfl_xor_sync(FULLM, pdB, 2);
            if ((lane & 3) == 0) {
                ALS[(size_t)row0 * HEADS + head] = psA;
                ALD[(size_t)row0 * HEADS + head] = pdA;
                ALS[(size_t)(row0 + 8) * HEADS + head] = psB;
                ALD[(size_t)(row0 + 8) * HEADS + head] = pdB;
            }
        }
    } else {
        constexpr int PT = 132;
        float* T = (float*)smem;
#pragma unroll
        for (int mi = 0; mi < 4; mi++) {
            const int rl = mbase + mi * 16 + gr;
#pragma unroll
            for (int ni = 0; ni < 4; ni++) {
                const int gcol = nbase + ni * 8 + qc;
                float* cc = c[mi][ni];
                float t0 = tanh_fast(cc[0] + scr[gcol]);
                float t1 = tanh_fast(cc[1] + scr[gcol + 1]);
                float t2 = tanh_fast(cc[2] + scr[gcol]);
                float t3 = tanh_fast(cc[3] + scr[gcol + 1]);
                *(float2*)&T[rl * PT + gcol] = make_float2(t0, t1);
                *(float2*)&T[(rl + 8) * PT + gcol] = make_float2(t2, t3);
            }
        }
        __syncthreads();
        {
            const int row  = t >> 1;
            const int half = t & 1;
            float acc[8];
#pragma unroll
            for (int o = 0; o < 8; o++) acc[o] = 0.f;
            const float* Tr = T + row * PT + half * 64;
            const float* W2s = scr + 128;
#pragma unroll 4
            for (int k = 0; k < 64; k++) {
                float tv = Tr[k];
                const float* w = W2s + (half * 64 + k) * 8;
                float4 wa = *(const float4*)w;
                float4 wb = *(const float4*)(w + 4);
                acc[0] = fmaf(tv, wa.x, acc[0]); acc[1] = fmaf(tv, wa.y, acc[1]);
                acc[2] = fmaf(tv, wa.z, acc[2]); acc[3] = fmaf(tv, wa.w, acc[3]);
                acc[4] = fmaf(tv, wb.x, acc[4]); acc[5] = fmaf(tv, wb.y, acc[5]);
                acc[6] = fmaf(tv, wb.z, acc[6]); acc[7] = fmaf(tv, wb.w, acc[7]);
            }
#pragma unroll
            for (int o = 0; o < 8; o++) acc[o] += __shfl_xor_sync(FULLM, acc[o], 1);
            if (half == 0) {
                float4 oa = make_float4(acc[0] + bm2[0], acc[1] + bm2[1],
                                        acc[2] + bm2[2], acc[3] + bm2[3]);
                float4 ob = make_float4(acc[4] + bm2[4], acc[5] + bm2[5],
                                        acc[6] + bm2[6], acc[7] + bm2[7]);
                *(float4*)&OUT[(size_t)(r0 + row) * DOUT + 0] = oa;
                *(float4*)&OUT[(size_t)(r0 + row) * DOUT + 4] = ob;
            }
        }
    }
}

// =====================================================================
// GAT aggregate v2: block per batch, 512 threads. H tile staged in smem
// (128 KB) — gathers become LDS, H global traffic 11x -> 1x.
// =====================================================================
__global__ __launch_bounds__(512) void gat_aggregate(
    const float* __restrict__ H, const float* __restrict__ ALS,
    const float* __restrict__ ALD,
    const float* __restrict__ bias, float* __restrict__ Xout)
{
    extern __shared__ __align__(16) char dsm[];
    float* sH = (float*)dsm;                 // 256*128 floats = 128 KB
    float* sS = sH + Nn * HID;               // 256*4
    float* sD = sS + Nn * HEADS;             // 256*4
    float* sb = sD + Nn * HEADS;             // 128

    const int b = blockIdx.x;
    const int base = b * Nn;
    const int t = threadIdx.x, wid = t >> 5, lane = t & 31;

    {
        const float4* src = (const float4*)(H + (size_t)base * HID);
        float4* dst = (float4*)sH;
        for (int idx = t; idx < Nn * HID / 4; idx += 512) dst[idx] = src[idx];
        const float4* srcS = (const float4*)(ALS + (size_t)base * HEADS);
        const float4* srcD = (const float4*)(ALD + (size_t)base * HEADS);
        for (int idx = t; idx < Nn; idx += 512) {
            ((float4*)sS)[idx] = srcS[idx];
            ((float4*)sD)[idx] = srcD[idx];
        }
        if (t < HID) sb[t] = bias[t];
    }
    __syncthreads();

    for (int nb = 0; nb < 16; nb++) {
        const int j = wid * 16 + nb;                 // local node 0..255
        const int d = g_rdeg[base + j];
        const uint8_t* adj = g_adj8 + (size_t)(base + j) * CAP;
        int n0 = (lane < d)      ? (int)adj[lane]      : -1;
        int n1 = (lane + 32 < d) ? (int)adj[lane + 32] : -1;

        const float4 aldj = *(const float4*)&sD[j * HEADS];

        float e00 = -3.0e38f, e01 = -3.0e38f, e02 = -3.0e38f, e03 = -3.0e38f;
        float e10 = -3.0e38f, e11 = -3.0e38f, e12 = -3.0e38f, e13 = -3.0e38f;
        if (n0 >= 0) {
            float4 s = *(const float4*)&sS[n0 * HEADS];
            e00 = lrelu(s.x + aldj.x); e01 = lrelu(s.y + aldj.y);
            e02 = lrelu(s.z + aldj.z); e03 = lrelu(s.w + aldj.w);
        }
        if (n1 >= 0) {
            float4 s = *(const float4*)&sS[n1 * HEADS];
            e10 = lrelu(s.x + aldj.x); e11 = lrelu(s.y + aldj.y);
            e12 = lrelu(s.z + aldj.z); e13 = lrelu(s.w + aldj.w);
        }

        float a00, a01, a02, a03, a10, a11, a12, a13;
#define SOFTMAX_HEAD(E0, E1, A0, A1)                                            \
        {                                                                       \
            float m = fmaxf(E0, E1);                                            \
            for (int o = 16; o; o >>= 1) m = fmaxf(m, __shfl_xor_sync(FULLM, m, o)); \
            float p0 = (n0 >= 0) ? __expf(E0 - m) : 0.f;                        \
            float p1 = (n1 >= 0) ? __expf(E1 - m) : 0.f;                        \
            float s = p0 + p1;                                                  \
            for (int o = 16; o; o >>= 1) s += __shfl_xor_sync(FULLM, s, o);     \
            float inv = 1.f / (s + 1e-16f);                                     \
            A0 = p0 * inv; A1 = p1 * inv;                                       \
        }
        SOFTMAX_HEAD(e00, e10, a00, a10)
        SOFTMAX_HEAD(e01, e11, a01, a11)
        SOFTMAX_HEAD(e02, e12, a02, a12)
        SOFTMAX_HEAD(e03, e13, a03, a13)
#undef SOFTMAX_HEAD

        float acc0 = 0.f, acc1 = 0.f, acc2 = 0.f, acc3 = 0.f;
        const int dlo = (d < 32) ? d : 32;
        for (int e = 0; e < dlo; e++) {
            int   i  = __shfl_sync(FULLM, n0,  e);
            float w0 = __shfl_sync(FULLM, a00, e);
            float w1 = __shfl_sync(FULLM, a01, e);
            float w2 = __shfl_sync(FULLM, a02, e);
            float w3 = __shfl_sync(FULLM, a03, e);
            const float* hp = sH + i * HID + lane;
            acc0 = fmaf(w0, hp[ 0], acc0);
            acc1 = fmaf(w1, hp[32], acc1);
            acc2 = fmaf(w2, hp[64], acc2);
            acc3 = fmaf(w3, hp[96], acc3);
        }
        for (int e = 32; e < d; e++) {
            int   i  = __shfl_sync(FULLM, n1,  e - 32);
            float w0 = __shfl_sync(FULLM, a10, e - 32);
            float w1 = __shfl_sync(FULLM, a11, e - 32);
            float w2 = __shfl_sync(FULLM, a12, e - 32);
            float w3 = __shfl_sync(FULLM, a13, e - 32);
            const float* hp = sH + i * HID + lane;
            acc0 = fmaf(w0, hp[ 0], acc0);
            acc1 = fmaf(w1, hp[32], acc1);
            acc2 = fmaf(w2, hp[64], acc2);
            acc3 = fmaf(w3, hp[96], acc3);
        }

        float* xp = Xout + (size_t)(base + j) * HID + lane;
        xp[ 0] = fmaxf(acc0 + sb[lane +  0], 0.f);
        xp[32] = fmaxf(acc1 + sb[lane + 32], 0.f);
        xp[64] = fmaxf(acc2 + sb[lane + 64], 0.f);
        xp[96] = fmaxf(acc3 + sb[lane + 96], 0.f);
    }
}

// =====================================================================
// Launcher
// =====================================================================
extern "C" void kernel_launch(void* const* d_in, const int* in_sizes, int n_in,
                              void* d_out, int out_size)
{
    const float* obs    = (const float*)d_in[0];
    const float* W1     = (const float*)d_in[1];
    const float* a1_src = (const float*)d_in[2];
    const float* a1_dst = (const float*)d_in[3];
    const float* b1     = (const float*)d_in[4];
    const float* W2     = (const float*)d_in[5];
    const float* a2_src = (const float*)d_in[6];
    const float* a2_dst = (const float*)d_in[7];
    const float* b2     = (const float*)d_in[8];
    const float* Wm1    = (const float*)d_in[9];
    const float* bm1    = (const float*)d_in[10];
    const float* Wm2    = (const float*)d_in[11];
    const float* bm2    = (const float*)d_in[12];
    float* out = (float*)d_out;

    float* hbuf; cudaGetSymbolAddress((void**)&hbuf, g_hbuf);
    float* xbuf; cudaGetSymbolAddress((void**)&xbuf, g_xbuf);
    float* als;  cudaGetSymbolAddress((void**)&als,  g_als);
    float* ald;  cudaGetSymbolAddress((void**)&ald,  g_ald);
    __nv_bfloat16 *w1h, *w1l, *w2h, *w2l, *wm1h, *wm1l;
    cudaGetSymbolAddress((void**)&w1h,  g_w1_hi);
    cudaGetSymbolAddress((void**)&w1l,  g_w1_lo);
    cudaGetSymbolAddress((void**)&w2h,  g_w2_hi);
    cudaGetSymbolAddress((void**)&w2l,  g_w2_lo);
    cudaGetSymbolAddress((void**)&wm1h, g_wm1_hi);
    cudaGetSymbolAddress((void**)&wm1l, g_wm1_lo);

    const int SMEM32  = 4 * 128 * (DIN + 8) * 2 + 8 * 1024;
    const int SMEM128 = 4 * 128 * (HID + 8) * 2 + 8 * 1024;
    const int SMEM_AGG = (Nn * HID + 2 * Nn * HEADS + HID) * 4;   // 136.5 KB
    cudaFuncSetAttribute(mma_gemm<DIN, 0>, cudaFuncAttributeMaxDynamicSharedMemorySize, SMEM32);
    cudaFuncSetAttribute(mma_gemm<HID, 0>, cudaFuncAttributeMaxDynamicSharedMemorySize, SMEM128);
    cudaFuncSetAttribute(mma_gemm<HID, 1>, cudaFuncAttributeMaxDynamicSharedMemorySize, SMEM128);
    cudaFuncSetAttribute(gat_aggregate, cudaFuncAttributeMaxDynamicSharedMemorySize, SMEM_AGG);

    const int GEMM_BLOCKS = NODES / 128;     // 1024

    prep_w_kernel<<<(DIN * 128 + 255) / 256, 256>>>(W1,  DIN, w1h,  w1l);
    prep_w_kernel<<<(HID * 128 + 255) / 256, 256>>>(W2,  HID, w2h,  w2l);
    prep_w_kernel<<<(HID * 128 + 255) / 256, 256>>>(Wm1, HID, wm1h, wm1l);

    knn_kernel<<<Bsz, 512>>>(obs);

    mma_gemm<DIN, 0><<<GEMM_BLOCKS, 256, SMEM32>>>(obs, w1h, w1l, a1_src, a1_dst,
        nullptr, nullptr, nullptr, hbuf, als, ald, nullptr);
    gat_aggregate<<<Bsz, 512, SMEM_AGG>>>(hbuf, als, ald, b1, xbuf);

    mma_gemm<HID, 0><<<GEMM_BLOCKS, 256, SMEM128>>>(xbuf, w2h, w2l, a2_src, a2_dst,
        nullptr, nullptr, nullptr, hbuf, als, ald, nullptr);
    gat_aggregate<<<Bsz, 512, SMEM_AGG>>>(hbuf, als, ald, b2, xbuf);

    mma_gemm<HID, 1><<<GEMM_BLOCKS, 256, SMEM128>>>(xbuf, wm1h, wm1l, nullptr, nullptr,
        bm1, Wm2, bm2, nullptr, nullptr, nullptr, out);
}

// round 10
// speedup vs baseline: 1.2616x; 1.2616x over previous
#include <cuda_runtime.h>
#include <cuda_bf16.h>
#include <cstdint>
#include <math.h>

#define Bsz   512
#define Nn    256
#define NODES (Bsz * Nn)      // 131072
#define DIN   32
#define HID   128
#define HEADS 4
#define Knn   5
#define DOUT  8
#define CAP   40
#define NEG_SLOPE 0.2f
#define FULLM 0xffffffffu

// ---------------- static device scratch ----------------
__device__ int     g_rdeg[NODES];
__device__ uint8_t g_adj8[(size_t)NODES * CAP];     // local (in-batch) indices
__device__ float   g_hbuf[(size_t)NODES * HID];
__device__ float   g_xbuf[(size_t)NODES * HID];
__device__ float   g_als[(size_t)NODES * HEADS];
__device__ float   g_ald[(size_t)NODES * HEADS];
// bf16 hi/lo images of W^T: [n=128 rows][k] row-major
__device__ __nv_bfloat16 g_w1_hi[128 * DIN],  g_w1_lo[128 * DIN];
__device__ __nv_bfloat16 g_w2_hi[128 * HID],  g_w2_lo[128 * HID];
__device__ __nv_bfloat16 g_wm1_hi[128 * HID], g_wm1_lo[128 * HID];

__device__ __forceinline__ float tanh_fast(float x) {
    return __fdividef(2.f, 1.f + __expf(-2.f * x)) - 1.f;
}
__device__ __forceinline__ float lrelu(float v) {
    return (v > 0.f) ? v : NEG_SLOPE * v;
}
__device__ __forceinline__ uint32_t smem_u32(const void* p) {
    uint32_t a;
    asm("{ .reg .u64 t; cvta.to.shared.u64 t, %1; cvt.u32.u64 %0, t; }" : "=r"(a) : "l"(p));
    return a;
}
__device__ __forceinline__ void ldsm_x4(uint32_t* r, uint32_t addr) {
    asm volatile("ldmatrix.sync.aligned.m8n8.x4.shared.b16 {%0,%1,%2,%3}, [%4];"
                 : "=r"(r[0]), "=r"(r[1]), "=r"(r[2]), "=r"(r[3]) : "r"(addr));
}
__device__ __forceinline__ void ldsm_x2(uint32_t* r, uint32_t addr) {
    asm volatile("ldmatrix.sync.aligned.m8n8.x2.shared.b16 {%0,%1}, [%2];"
                 : "=r"(r[0]), "=r"(r[1]) : "r"(addr));
}
__device__ __forceinline__ void mma_bf16(float* c, const uint32_t* a, const uint32_t* b) {
    asm volatile("mma.sync.aligned.m16n8k16.row.col.f32.bf16.bf16.f32 "
                 "{%0,%1,%2,%3}, {%4,%5,%6,%7}, {%8,%9}, {%0,%1,%2,%3};"
                 : "+f"(c[0]), "+f"(c[1]), "+f"(c[2]), "+f"(c[3])
                 : "r"(a[0]), "r"(a[1]), "r"(a[2]), "r"(a[3]), "r"(b[0]), "r"(b[1]));
}
__device__ __forceinline__ uint32_t pack_bf2(__nv_bfloat16 a, __nv_bfloat16 b) {
    return (uint32_t)__bfloat16_as_ushort(a) | ((uint32_t)__bfloat16_as_ushort(b) << 16);
}

// =====================================================================
// Prep: W [K,128] -> hi/lo bf16 images of W^T [128][K]
// =====================================================================
__global__ void prep_w_kernel(const float* __restrict__ W, int K,
                              __nv_bfloat16* __restrict__ hi, __nv_bfloat16* __restrict__ lo)
{
    int idx = blockIdx.x * blockDim.x + threadIdx.x;
    if (idx >= K * 128) return;
    int k = idx >> 7, n = idx & 127;
    float x = W[idx];
    __nv_bfloat16 h = __float2bfloat16(x);
    __nv_bfloat16 l = __float2bfloat16(x - __bfloat162float(h));
    hi[n * K + k] = h;
    lo[n * K + k] = l;
}

// =====================================================================
// KNN v2 (kept — measured 71 -> 55 us): block per batch, 512 threads.
// =====================================================================
__global__ __launch_bounds__(512) void knn_kernel(const float* __restrict__ obs)
{
    __shared__ float   sx[Nn];
    __shared__ float   sy[Nn];
    __shared__ int     sdeg[Nn];
    __shared__ uint8_t sadj[Nn * CAP];
    __shared__ float   mbd[Nn * 2 * Knn];
    __shared__ int     mbi[Nn * 2 * Knn];

    const int b = blockIdx.x;
    const int t = threadIdx.x;
    const int n = t & (Nn - 1);
    const int half = t >> 8;

    if (t < Nn) {
        const size_t base = ((size_t)b * Nn + n) * DIN;
        sx[n] = obs[base + 0];
        sy[n] = obs[base + 1];
        sdeg[n] = 1;
        sadj[n * CAP + 0] = (uint8_t)n;
    }
    __syncthreads();

    const float px = sx[n], py = sy[n];
    float bd[Knn];
    int   bi[Knn];
#pragma unroll
    for (int s = 0; s < Knn; s++) { bd[s] = 3.0e38f; bi[s] = -1; }

    const int j0 = half * 128;
    for (int jj = 0; jj < 128; jj++) {
        const int j = j0 + jj;
        float dx = sx[j] - px;
        float dy = sy[j] - py;
        float d  = fmaf(dx, dx, dy * dy);
        if (j == n) d = 3.0e38f;
        if (d < bd[Knn - 1]) {
            bd[Knn - 1] = d; bi[Knn - 1] = j;
#pragma unroll
            for (int s = Knn - 2; s >= 0; s--) {
                if (bd[s + 1] < bd[s]) {
                    float td = bd[s]; bd[s] = bd[s + 1]; bd[s + 1] = td;
                    int   ti = bi[s]; bi[s] = bi[s + 1]; bi[s + 1] = ti;
                }
            }
        }
    }
#pragma unroll
    for (int s = 0; s < Knn; s++) {
        mbd[(n * 2 + half) * Knn + s] = bd[s];
        mbi[(n * 2 + half) * Knn + s] = bi[s];
    }
    __syncthreads();

    if (t < Nn) {
        const float* A  = &mbd[(n * 2 + 0) * Knn];
        const float* B  = &mbd[(n * 2 + 1) * Knn];
        const int*   Ai = &mbi[(n * 2 + 0) * Knn];
        const int*   Bi = &mbi[(n * 2 + 1) * Knn];
        int ia = 0, ib = 0;
#pragma unroll
        for (int s = 0; s < Knn; s++) {
            int jn;
            if (A[ia] <= B[ib]) jn = Ai[ia++];
            else                jn = Bi[ib++];
            int p = atomicAdd(&sdeg[jn], 1);
            if (p < CAP) sadj[jn * CAP + p] = (uint8_t)n;
        }
    }
    __syncthreads();

    if (t < Nn) {
        int deg = min(sdeg[n], CAP);
        g_rdeg[b * Nn + n] = deg;
        uint8_t* dst = g_adj8 + (size_t)(b * Nn + n) * CAP;
        const uint32_t* srcw = (const uint32_t*)&sadj[n * CAP];
#pragma unroll
        for (int w = 0; w < CAP / 4; w++)
            ((uint32_t*)dst)[w] = srcw[w];
    }
}

// =====================================================================
// mma.sync GEMM (unchanged; passing since round 6)
// =====================================================================
template<int KDIM, int MODE>
__global__ __launch_bounds__(256) void mma_gemm(
    const float* __restrict__ X,
    const __nv_bfloat16* __restrict__ gBhi, const __nv_bfloat16* __restrict__ gBlo,
    const float* __restrict__ asrc, const float* __restrict__ adst,
    const float* __restrict__ bias, const float* __restrict__ Wm2,
    const float* __restrict__ bm2,
    float* __restrict__ H, float* __restrict__ ALS, float* __restrict__ ALD,
    float* __restrict__ OUT)
{
    constexpr int PK = KDIM + 8;
    extern __shared__ __align__(16) char smem[];
    __nv_bfloat16* sAhi = (__nv_bfloat16*)smem;
    __nv_bfloat16* sAlo = sAhi + 128 * PK;
    __nv_bfloat16* sBhi = sAlo + 128 * PK;
    __nv_bfloat16* sBlo = sBhi + 128 * PK;
    float* scr = (float*)(sBlo + 128 * PK);

    const int t = threadIdx.x, wid = t >> 5, lane = t & 31;
    const int r0 = blockIdx.x * 128;

    if (MODE == 0) {
        if (t < 128) { scr[t] = asrc[t]; scr[128 + t] = adst[t]; }
    } else {
        if (t < 128) scr[t] = bias[t];
        for (int e = t; e < 1024; e += 256) scr[128 + e] = Wm2[e];
    }

    for (int idx = t; idx < 128 * (KDIM / 2); idx += 256) {
        int row = idx / (KDIM / 2);
        int k   = (idx % (KDIM / 2)) * 2;
        float2 v = *(const float2*)&X[(size_t)(r0 + row) * KDIM + k];
        __nv_bfloat16 h0 = __float2bfloat16(v.x);
        __nv_bfloat16 h1 = __float2bfloat16(v.y);
        __nv_bfloat16 l0 = __float2bfloat16(v.x - __bfloat162float(h0));
        __nv_bfloat16 l1 = __float2bfloat16(v.y - __bfloat162float(h1));
        *(uint32_t*)&sAhi[row * PK + k] = pack_bf2(h0, h1);
        *(uint32_t*)&sAlo[row * PK + k] = pack_bf2(l0, l1);
    }
    for (int idx = t; idx < 128 * (KDIM / 8); idx += 256) {
        int n  = idx / (KDIM / 8);
        int kc = (idx % (KDIM / 8)) * 8;
        *(float4*)&sBhi[n * PK + kc] = *(const float4*)&gBhi[n * KDIM + kc];
        *(float4*)&sBlo[n * PK + kc] = *(const float4*)&gBlo[n * KDIM + kc];
    }
    __syncthreads();

    const int mbase = (wid & 1) * 64;
    const int nbase = (wid >> 1) * 32;

    float c[4][4][4];
#pragma unroll
    for (int mi = 0; mi < 4; mi++)
#pragma unroll
        for (int ni = 0; ni < 4; ni++)
#pragma unroll
            for (int q = 0; q < 4; q++) c[mi][ni][q] = 0.f;

    const int arow = mbase + (lane & 7) + ((lane >> 3) & 1) * 8;
    const int ak   = (lane >> 4) * 8;
    const int brow = nbase + (lane & 7);
    const int bk   = ((lane >> 3) & 1) * 8;

#pragma unroll
    for (int p = 0; p < 3; p++) {
        const __nv_bfloat16* A  = (p == 2) ? sAlo : sAhi;
        const __nv_bfloat16* Bm = (p == 1) ? sBlo : sBhi;
#pragma unroll
        for (int ks = 0; ks < KDIM / 16; ks++) {
            uint32_t a[4][4], b[4][2];
#pragma unroll
            for (int mi = 0; mi < 4; mi++)
                ldsm_x4(a[mi], smem_u32(&A[(arow + mi * 16) * PK + ks * 16 + ak]));
#pragma unroll
            for (int ni = 0; ni < 4; ni++)
                ldsm_x2(b[ni], smem_u32(&Bm[(brow + ni * 8) * PK + ks * 16 + bk]));
#pragma unroll
            for (int mi = 0; mi < 4; mi++)
#pragma unroll
                for (int ni = 0; ni < 4; ni++)
                    mma_bf16(c[mi][ni], a[mi], b[ni]);
        }
    }
    __syncthreads();

    const int gr = lane >> 2;
    const int qc = (lane & 3) * 2;

    if (MODE == 0) {
        const int head = wid >> 1;
#pragma unroll
        for (int mi = 0; mi < 4; mi++) {
            const int row0 = r0 + mbase + mi * 16 + gr;
            float psA = 0.f, pdA = 0.f, psB = 0.f, pdB = 0.f;
#pragma unroll
            for (int ni = 0; ni < 4; ni++) {
                const int gcol = nbase + ni * 8 + qc;
                float* cc = c[mi][ni];
                *(float2*)&H[(size_t)row0 * HID + gcol] = make_float2(cc[0], cc[1]);
                *(float2*)&H[(size_t)(row0 + 8) * HID + gcol] = make_float2(cc[2], cc[3]);
                psA = fmaf(cc[0], scr[gcol], fmaf(cc[1], scr[gcol + 1], psA));
                pdA = fmaf(cc[0], scr[128 + gcol], fmaf(cc[1], scr[128 + gcol + 1], pdA));
                psB = fmaf(cc[2], scr[gcol], fmaf(cc[3], scr[gcol + 1], psB));
                pdB = fmaf(cc[2], scr[128 + gcol], fmaf(cc[3], scr[128 + gcol + 1], pdB));
            }
            psA += __shfl_xor_sync(FULLM, psA, 1); psA += __shfl_xor_sync(FULLM, psA, 2);
            pdA += __shfl_xor_sync(FULLM, pdA, 1); pdA += __shfl_xor_sync(FULLM, pdA, 2);
            psB += __shfl_xor_sync(FULLM, psB, 1); psB += __shfl_xor_sync(FULLM, psB, 2);
            pdB += __shfl_xor_sync(FULLM, pdB, 1); pdB += __shfl_xor_sync(FULLM, pdB, 2);
            if ((lane & 3) == 0) {
                ALS[(size_t)row0 * HEADS + head] = psA;
                ALD[(size_t)row0 * HEADS + head] = pdA;
                ALS[(size_t)(row0 + 8) * HEADS + head] = psB;
                ALD[(size_t)(row0 + 8) * HEADS + head] = pdB;
            }
        }
    } else {
        constexpr int PT = 132;
        float* T = (float*)smem;
#pragma unroll
        for (int mi = 0; mi < 4; mi++) {
            const int rl = mbase + mi * 16 + gr;
#pragma unroll
            for (int ni = 0; ni < 4; ni++) {
                const int gcol = nbase + ni * 8 + qc;
                float* cc = c[mi][ni];
                float t0 = tanh_fast(cc[0] + scr[gcol]);
                float t1 = tanh_fast(cc[1] + scr[gcol + 1]);
                float t2 = tanh_fast(cc[2] + scr[gcol]);
                float t3 = tanh_fast(cc[3] + scr[gcol + 1]);
                *(float2*)&T[rl * PT + gcol] = make_float2(t0, t1);
                *(float2*)&T[(rl + 8) * PT + gcol] = make_float2(t2, t3);
            }
        }
        __syncthreads();
        {
            const int row  = t >> 1;
            const int half = t & 1;
            float acc[8];
#pragma unroll
            for (int o = 0; o < 8; o++) acc[o] = 0.f;
            const float* Tr = T + row * PT + half * 64;
            const float* W2s = scr + 128;
#pragma unroll 4
            for (int k = 0; k < 64; k++) {
                float tv = Tr[k];
                const float* w = W2s + (half * 64 + k) * 8;
                float4 wa = *(const float4*)w;
                float4 wb = *(const float4*)(w + 4);
                acc[0] = fmaf(tv, wa.x, acc[0]); acc[1] = fmaf(tv, wa.y, acc[1]);
                acc[2] = fmaf(tv, wa.z, acc[2]); acc[3] = fmaf(tv, wa.w, acc[3]);
                acc[4] = fmaf(tv, wb.x, acc[4]); acc[5] = fmaf(tv, wb.y, acc[5]);
                acc[6] = fmaf(tv, wb.z, acc[6]); acc[7] = fmaf(tv, wb.w, acc[7]);
            }
#pragma unroll
            for (int o = 0; o < 8; o++) acc[o] += __shfl_xor_sync(FULLM, acc[o], 1);
            if (half == 0) {
                float4 oa = make_float4(acc[0] + bm2[0], acc[1] + bm2[1],
                                        acc[2] + bm2[2], acc[3] + bm2[3]);
                float4 ob = make_float4(acc[4] + bm2[4], acc[5] + bm2[5],
                                        acc[6] + bm2[6], acc[7] + bm2[7]);
                *(float4*)&OUT[(size_t)(r0 + row) * DOUT + 0] = oa;
                *(float4*)&OUT[(size_t)(r0 + row) * DOUT + 4] = ob;
            }
        }
    }
}

// =====================================================================
// GAT aggregate — REVERTED to round-6 warp-per-node form (measured
// faster than block-per-batch smem staging), now with uint8 adjacency.
// =====================================================================
__global__ __launch_bounds__(256) void gat_aggregate(
    const float* __restrict__ H, const float* __restrict__ ALS,
    const float* __restrict__ ALD,
    const float* __restrict__ bias, float* __restrict__ Xout)
{
    const int j    = (blockIdx.x * blockDim.x + threadIdx.x) >> 5;   // global node
    const int lane = threadIdx.x & 31;
    const int base = (j >> 8) << 8;                                  // batch start

    const int d = g_rdeg[j];
    const uint8_t* adj = g_adj8 + (size_t)j * CAP;
    int n0 = (lane < d)      ? base + (int)adj[lane]      : -1;
    int n1 = (lane + 32 < d) ? base + (int)adj[lane + 32] : -1;

    const float4 aldj = *(const float4*)&ALD[(size_t)j * HEADS];

    float e00 = -3.0e38f, e01 = -3.0e38f, e02 = -3.0e38f, e03 = -3.0e38f;
    float e10 = -3.0e38f, e11 = -3.0e38f, e12 = -3.0e38f, e13 = -3.0e38f;
    if (n0 >= 0) {
        float4 s = *(const float4*)&ALS[(size_t)n0 * HEADS];
        e00 = lrelu(s.x + aldj.x); e01 = lrelu(s.y + aldj.y);
        e02 = lrelu(s.z + aldj.z); e03 = lrelu(s.w + aldj.w);
    }
    if (n1 >= 0) {
        float4 s = *(const float4*)&ALS[(size_t)n1 * HEADS];
        e10 = lrelu(s.x + aldj.x); e11 = lrelu(s.y + aldj.y);
        e12 = lrelu(s.z + aldj.z); e13 = lrelu(s.w + aldj.w);
    }

    float a00, a01, a02, a03, a10, a11, a12, a13;
#define SOFTMAX_HEAD(E0, E1, A0, A1)                                        \
    {                                                                       \
        float m = fmaxf(E0, E1);                                            \
        for (int o = 16; o; o >>= 1) m = fmaxf(m, __shfl_xor_sync(FULLM, m, o)); \
        float p0 = (n0 >= 0) ? __expf(E0 - m) : 0.f;                        \
        float p1 = (n1 >= 0) ? __expf(E1 - m) : 0.f;                        \
        float s = p0 + p1;                                                  \
        for (int o = 16; o; o >>= 1) s += __shfl_xor_sync(FULLM, s, o);     \
        float inv = 1.f / (s + 1e-16f);                                     \
        A0 = p0 * inv; A1 = p1 * inv;                                       \
    }
    SOFTMAX_HEAD(e00, e10, a00, a10)
    SOFTMAX_HEAD(e01, e11, a01, a11)
    SOFTMAX_HEAD(e02, e12, a02, a12)
    SOFTMAX_HEAD(e03, e13, a03, a13)
#undef SOFTMAX_HEAD

    float acc0 = 0.f, acc1 = 0.f, acc2 = 0.f, acc3 = 0.f;
    const int dlo = (d < 32) ? d : 32;
    for (int e = 0; e < dlo; e++) {
        int   i  = __shfl_sync(FULLM, n0,  e);
        float w0 = __shfl_sync(FULLM, a00, e);
        float w1 = __shfl_sync(FULLM, a01, e);
        float w2 = __shfl_sync(FULLM, a02, e);
        float w3 = __shfl_sync(FULLM, a03, e);
        const float* hp = H + (size_t)i * HID + lane;
        acc0 = fmaf(w0, __ldg(hp +  0), acc0);
        acc1 = fmaf(w1, __ldg(hp + 32), acc1);
        acc2 = fmaf(w2, __ldg(hp + 64), acc2);
        acc3 = fmaf(w3, __ldg(hp + 96), acc3);
    }
    for (int e = 32; e < d; e++) {
        int   i  = __shfl_sync(FULLM, n1,  e - 32);
        float w0 = __shfl_sync(FULLM, a10, e - 32);
        float w1 = __shfl_sync(FULLM, a11, e - 32);
        float w2 = __shfl_sync(FULLM, a12, e - 32);
        float w3 = __shfl_sync(FULLM, a13, e - 32);
        const float* hp = H + (size_t)i * HID + lane;
        acc0 = fmaf(w0, __ldg(hp +  0), acc0);
        acc1 = fmaf(w1, __ldg(hp + 32), acc1);
        acc2 = fmaf(w2, __ldg(hp + 64), acc2);
        acc3 = fmaf(w3, __ldg(hp + 96), acc3);
    }

    float* xp = Xout + (size_t)j * HID + lane;
    xp[ 0] = fmaxf(acc0 + bias[lane +  0], 0.f);
    xp[32] = fmaxf(acc1 + bias[lane + 32], 0.f);
    xp[64] = fmaxf(acc2 + bias[lane + 64], 0.f);
    xp[96] = fmaxf(acc3 + bias[lane + 96], 0.f);
}

// =====================================================================
// Launcher
// =====================================================================
extern "C" void kernel_launch(void* const* d_in, const int* in_sizes, int n_in,
                              void* d_out, int out_size)
{
    const float* obs    = (const float*)d_in[0];
    const float* W1     = (const float*)d_in[1];
    const float* a1_src = (const float*)d_in[2];
    const float* a1_dst = (const float*)d_in[3];
    const float* b1     = (const float*)d_in[4];
    const float* W2     = (const float*)d_in[5];
    const float* a2_src = (const float*)d_in[6];
    const float* a2_dst = (const float*)d_in[7];
    const float* b2     = (const float*)d_in[8];
    const float* Wm1    = (const float*)d_in[9];
    const float* bm1    = (const float*)d_in[10];
    const float* Wm2    = (const float*)d_in[11];
    const float* bm2    = (const float*)d_in[12];
    float* out = (float*)d_out;

    float* hbuf; cudaGetSymbolAddress((void**)&hbuf, g_hbuf);
    float* xbuf; cudaGetSymbolAddress((void**)&xbuf, g_xbuf);
    float* als;  cudaGetSymbolAddress((void**)&als,  g_als);
    float* ald;  cudaGetSymbolAddress((void**)&ald,  g_ald);
    __nv_bfloat16 *w1h, *w1l, *w2h, *w2l, *wm1h, *wm1l;
    cudaGetSymbolAddress((void**)&w1h,  g_w1_hi);
    cudaGetSymbolAddress((void**)&w1l,  g_w1_lo);
    cudaGetSymbolAddress((void**)&w2h,  g_w2_hi);
    cudaGetSymbolAddress((void**)&w2l,  g_w2_lo);
    cudaGetSymbolAddress((void**)&wm1h, g_wm1_hi);
    cudaGetSymbolAddress((void**)&wm1l, g_wm1_lo);

    const int SMEM32  = 4 * 128 * (DIN + 8) * 2 + 8 * 1024;
    const int SMEM128 = 4 * 128 * (HID + 8) * 2 + 8 * 1024;
    cudaFuncSetAttribute(mma_gemm<DIN, 0>, cudaFuncAttributeMaxDynamicSharedMemorySize, SMEM32);
    cudaFuncSetAttribute(mma_gemm<HID, 0>, cudaFuncAttributeMaxDynamicSharedMemorySize, SMEM128);
    cudaFuncSetAttribute(mma_gemm<HID, 1>, cudaFuncAttributeMaxDynamicSharedMemorySize, SMEM128);

    const int GEMM_BLOCKS = NODES / 128;     // 1024
    const int AGG_BLOCKS  = NODES / 8;       // 16384 (8 warps/block)

    prep_w_kernel<<<(DIN * 128 + 255) / 256, 256>>>(W1,  DIN, w1h,  w1l);
    prep_w_kernel<<<(HID * 128 + 255) / 256, 256>>>(W2,  HID, w2h,  w2l);
    prep_w_kernel<<<(HID * 128 + 255) / 256, 256>>>(Wm1, HID, wm1h, wm1l);

    knn_kernel<<<Bsz, 512>>>(obs);

    mma_gemm<DIN, 0><<<GEMM_BLOCKS, 256, SMEM32>>>(obs, w1h, w1l, a1_src, a1_dst,
        nullptr, nullptr, nullptr, hbuf, als, ald, nullptr);
    gat_aggregate<<<AGG_BLOCKS, 256>>>(hbuf, als, ald, b1, xbuf);

    mma_gemm<HID, 0><<<GEMM_BLOCKS, 256, SMEM128>>>(xbuf, w2h, w2l, a2_src, a2_dst,
        nullptr, nullptr, nullptr, hbuf, als, ald, nullptr);
    gat_aggregate<<<AGG_BLOCKS, 256>>>(hbuf, als, ald, b2, xbuf);

    mma_gemm<HID, 1><<<GEMM_BLOCKS, 256, SMEM128>>>(xbuf, wm1h, wm1l, nullptr, nullptr,
        bm1, Wm2, bm2, nullptr, nullptr, nullptr, out);
}

// round 11
// speedup vs baseline: 1.2946x; 1.0261x over previous
#include <cuda_runtime.h>
#include <cuda_bf16.h>
#include <cstdint>
#include <math.h>

#define Bsz   512
#define Nn    256
#define NODES (Bsz * Nn)      // 131072
#define DIN   32
#define HID   128
#define HEADS 4
#define Knn   5
#define DOUT  8
#define CAP   40
#define NEG_SLOPE 0.2f
#define FULLM 0xffffffffu
#define NTILES (NODES / 128)  // 1024

// ---------------- static device scratch ----------------
__device__ int     g_rdeg[NODES];
__device__ uint8_t g_adj8[(size_t)NODES * CAP];     // local (in-batch) indices
__device__ float   g_hbuf[(size_t)NODES * HID];
__device__ float   g_xbuf[(size_t)NODES * HID];
__device__ float   g_als[(size_t)NODES * HEADS];
__device__ float   g_ald[(size_t)NODES * HEADS];
// bf16 hi/lo images of W^T: [n=128 rows][k] row-major
__device__ __nv_bfloat16 g_w1_hi[128 * DIN],  g_w1_lo[128 * DIN];
__device__ __nv_bfloat16 g_w2_hi[128 * HID],  g_w2_lo[128 * HID];
__device__ __nv_bfloat16 g_wm1_hi[128 * HID], g_wm1_lo[128 * HID];

__device__ __forceinline__ float tanh_fast(float x) {
    return __fdividef(2.f, 1.f + __expf(-2.f * x)) - 1.f;
}
__device__ __forceinline__ float lrelu(float v) {
    return (v > 0.f) ? v : NEG_SLOPE * v;
}
__device__ __forceinline__ uint32_t smem_u32(const void* p) {
    uint32_t a;
    asm("{ .reg .u64 t; cvta.to.shared.u64 t, %1; cvt.u32.u64 %0, t; }" : "=r"(a) : "l"(p));
    return a;
}
__device__ __forceinline__ void ldsm_x4(uint32_t* r, uint32_t addr) {
    asm volatile("ldmatrix.sync.aligned.m8n8.x4.shared.b16 {%0,%1,%2,%3}, [%4];"
                 : "=r"(r[0]), "=r"(r[1]), "=r"(r[2]), "=r"(r[3]) : "r"(addr));
}
__device__ __forceinline__ void ldsm_x2(uint32_t* r, uint32_t addr) {
    asm volatile("ldmatrix.sync.aligned.m8n8.x2.shared.b16 {%0,%1}, [%2];"
                 : "=r"(r[0]), "=r"(r[1]) : "r"(addr));
}
__device__ __forceinline__ void mma_bf16(float* c, const uint32_t* a, const uint32_t* b) {
    asm volatile("mma.sync.aligned.m16n8k16.row.col.f32.bf16.bf16.f32 "
                 "{%0,%1,%2,%3}, {%4,%5,%6,%7}, {%8,%9}, {%0,%1,%2,%3};"
                 : "+f"(c[0]), "+f"(c[1]), "+f"(c[2]), "+f"(c[3])
                 : "r"(a[0]), "r"(a[1]), "r"(a[2]), "r"(a[3]), "r"(b[0]), "r"(b[1]));
}
__device__ __forceinline__ uint32_t pack_bf2(__nv_bfloat16 a, __nv_bfloat16 b) {
    return (uint32_t)__bfloat16_as_ushort(a) | ((uint32_t)__bfloat16_as_ushort(b) << 16);
}

// =====================================================================
// Prep: W [K,128] -> hi/lo bf16 images of W^T [128][K]
// =====================================================================
__global__ void prep_w_kernel(const float* __restrict__ W, int K,
                              __nv_bfloat16* __restrict__ hi, __nv_bfloat16* __restrict__ lo)
{
    int idx = blockIdx.x * blockDim.x + threadIdx.x;
    if (idx >= K * 128) return;
    int k = idx >> 7, n = idx & 127;
    float x = W[idx];
    __nv_bfloat16 h = __float2bfloat16(x);
    __nv_bfloat16 l = __float2bfloat16(x - __bfloat162float(h));
    hi[n * K + k] = h;
    lo[n * K + k] = l;
}

// =====================================================================
// KNN v2 (measured 55 us): block per batch, 512 threads.
// =====================================================================
__global__ __launch_bounds__(512) void knn_kernel(const float* __restrict__ obs)
{
    __shared__ float   sx[Nn];
    __shared__ float   sy[Nn];
    __shared__ int     sdeg[Nn];
    __shared__ uint8_t sadj[Nn * CAP];
    __shared__ float   mbd[Nn * 2 * Knn];
    __shared__ int     mbi[Nn * 2 * Knn];

    const int b = blockIdx.x;
    const int t = threadIdx.x;
    const int n = t & (Nn - 1);
    const int half = t >> 8;

    if (t < Nn) {
        const size_t base = ((size_t)b * Nn + n) * DIN;
        sx[n] = obs[base + 0];
        sy[n] = obs[base + 1];
        sdeg[n] = 1;
        sadj[n * CAP + 0] = (uint8_t)n;
    }
    __syncthreads();

    const float px = sx[n], py = sy[n];
    float bd[Knn];
    int   bi[Knn];
#pragma unroll
    for (int s = 0; s < Knn; s++) { bd[s] = 3.0e38f; bi[s] = -1; }

    const int j0 = half * 128;
    for (int jj = 0; jj < 128; jj++) {
        const int j = j0 + jj;
        float dx = sx[j] - px;
        float dy = sy[j] - py;
        float d  = fmaf(dx, dx, dy * dy);
        if (j == n) d = 3.0e38f;
        if (d < bd[Knn - 1]) {
            bd[Knn - 1] = d; bi[Knn - 1] = j;
#pragma unroll
            for (int s = Knn - 2; s >= 0; s--) {
                if (bd[s + 1] < bd[s]) {
                    float td = bd[s]; bd[s] = bd[s + 1]; bd[s + 1] = td;
                    int   ti = bi[s]; bi[s] = bi[s + 1]; bi[s + 1] = ti;
                }
            }
        }
    }
#pragma unroll
    for (int s = 0; s < Knn; s++) {
        mbd[(n * 2 + half) * Knn + s] = bd[s];
        mbi[(n * 2 + half) * Knn + s] = bi[s];
    }
    __syncthreads();

    if (t < Nn) {
        const float* A  = &mbd[(n * 2 + 0) * Knn];
        const float* B  = &mbd[(n * 2 + 1) * Knn];
        const int*   Ai = &mbi[(n * 2 + 0) * Knn];
        const int*   Bi = &mbi[(n * 2 + 1) * Knn];
        int ia = 0, ib = 0;
#pragma unroll
        for (int s = 0; s < Knn; s++) {
            int jn;
            if (A[ia] <= B[ib]) jn = Ai[ia++];
            else                jn = Bi[ib++];
            int p = atomicAdd(&sdeg[jn], 1);
            if (p < CAP) sadj[jn * CAP + p] = (uint8_t)n;
        }
    }
    __syncthreads();

    if (t < Nn) {
        int deg = min(sdeg[n], CAP);
        g_rdeg[b * Nn + n] = deg;
        uint8_t* dst = g_adj8 + (size_t)(b * Nn + n) * CAP;
        const uint32_t* srcw = (const uint32_t*)&sadj[n * CAP];
#pragma unroll
        for (int w = 0; w < CAP / 4; w++)
            ((uint32_t*)dst)[w] = srcw[w];
    }
}

// =====================================================================
// PERSISTENT mma.sync GEMM: B image loaded to smem ONCE per block,
// block loops over row tiles. Core mma path unchanged from round 6.
// =====================================================================
template<int KDIM, int MODE>
__global__ __launch_bounds__(256) void mma_gemm(
    const float* __restrict__ X,
    const __nv_bfloat16* __restrict__ gBhi, const __nv_bfloat16* __restrict__ gBlo,
    const float* __restrict__ asrc, const float* __restrict__ adst,
    const float* __restrict__ bias, const float* __restrict__ Wm2,
    const float* __restrict__ bm2,
    float* __restrict__ H, float* __restrict__ ALS, float* __restrict__ ALD,
    float* __restrict__ OUT)
{
    constexpr int PK = KDIM + 8;
    extern __shared__ __align__(16) char smem[];
    __nv_bfloat16* sAhi = (__nv_bfloat16*)smem;
    __nv_bfloat16* sAlo = sAhi + 128 * PK;
    __nv_bfloat16* sBhi = sAlo + 128 * PK;
    __nv_bfloat16* sBlo = sBhi + 128 * PK;
    float* scr = (float*)(sBlo + 128 * PK);

    const int t = threadIdx.x, wid = t >> 5, lane = t & 31;

    // ---- one-time setup: scr + B image ----
    if (MODE == 0) {
        if (t < 128) { scr[t] = asrc[t]; scr[128 + t] = adst[t]; }
    } else {
        if (t < 128) scr[t] = bias[t];
        for (int e = t; e < 1024; e += 256) scr[128 + e] = Wm2[e];
    }
    for (int idx = t; idx < 128 * (KDIM / 8); idx += 256) {
        int n  = idx / (KDIM / 8);
        int kc = (idx % (KDIM / 8)) * 8;
        *(float4*)&sBhi[n * PK + kc] = *(const float4*)&gBhi[n * KDIM + kc];
        *(float4*)&sBlo[n * PK + kc] = *(const float4*)&gBlo[n * KDIM + kc];
    }
    __syncthreads();

    const int mbase = (wid & 1) * 64;
    const int nbase = (wid >> 1) * 32;
    const int arow = mbase + (lane & 7) + ((lane >> 3) & 1) * 8;
    const int ak   = (lane >> 4) * 8;
    const int brow = nbase + (lane & 7);
    const int bk   = ((lane >> 3) & 1) * 8;
    const int gr = lane >> 2;
    const int qc = (lane & 3) * 2;

    for (int tile = blockIdx.x; tile < NTILES; tile += gridDim.x) {
        const int r0 = tile * 128;

        // ---- convert X tile -> sAhi/sAlo ----
        for (int idx = t; idx < 128 * (KDIM / 2); idx += 256) {
            int row = idx / (KDIM / 2);
            int k   = (idx % (KDIM / 2)) * 2;
            float2 v = *(const float2*)&X[(size_t)(r0 + row) * KDIM + k];
            __nv_bfloat16 h0 = __float2bfloat16(v.x);
            __nv_bfloat16 h1 = __float2bfloat16(v.y);
            __nv_bfloat16 l0 = __float2bfloat16(v.x - __bfloat162float(h0));
            __nv_bfloat16 l1 = __float2bfloat16(v.y - __bfloat162float(h1));
            *(uint32_t*)&sAhi[row * PK + k] = pack_bf2(h0, h1);
            *(uint32_t*)&sAlo[row * PK + k] = pack_bf2(l0, l1);
        }
        __syncthreads();

        // ---- mma: split-bf16 x3 ----
        float c[4][4][4];
#pragma unroll
        for (int mi = 0; mi < 4; mi++)
#pragma unroll
            for (int ni = 0; ni < 4; ni++)
#pragma unroll
                for (int q = 0; q < 4; q++) c[mi][ni][q] = 0.f;

#pragma unroll
        for (int p = 0; p < 3; p++) {
            const __nv_bfloat16* A  = (p == 2) ? sAlo : sAhi;
            const __nv_bfloat16* Bm = (p == 1) ? sBlo : sBhi;
#pragma unroll
            for (int ks = 0; ks < KDIM / 16; ks++) {
                uint32_t a[4][4], b[4][2];
#pragma unroll
                for (int mi = 0; mi < 4; mi++)
                    ldsm_x4(a[mi], smem_u32(&A[(arow + mi * 16) * PK + ks * 16 + ak]));
#pragma unroll
                for (int ni = 0; ni < 4; ni++)
                    ldsm_x2(b[ni], smem_u32(&Bm[(brow + ni * 8) * PK + ks * 16 + bk]));
#pragma unroll
                for (int mi = 0; mi < 4; mi++)
#pragma unroll
                    for (int ni = 0; ni < 4; ni++)
                        mma_bf16(c[mi][ni], a[mi], b[ni]);
            }
        }
        __syncthreads();

        // ---- epilogue ----
        if (MODE == 0) {
            const int head = wid >> 1;
#pragma unroll
            for (int mi = 0; mi < 4; mi++) {
                const int row0 = r0 + mbase + mi * 16 + gr;
                float psA = 0.f, pdA = 0.f, psB = 0.f, pdB = 0.f;
#pragma unroll
                for (int ni = 0; ni < 4; ni++) {
                    const int gcol = nbase + ni * 8 + qc;
                    float* cc = c[mi][ni];
                    *(float2*)&H[(size_t)row0 * HID + gcol] = make_float2(cc[0], cc[1]);
                    *(float2*)&H[(size_t)(row0 + 8) * HID + gcol] = make_float2(cc[2], cc[3]);
                    psA = fmaf(cc[0], scr[gcol], fmaf(cc[1], scr[gcol + 1], psA));
                    pdA = fmaf(cc[0], scr[128 + gcol], fmaf(cc[1], scr[128 + gcol + 1], pdA));
                    psB = fmaf(cc[2], scr[gcol], fmaf(cc[3], scr[gcol + 1], psB));
                    pdB = fmaf(cc[2], scr[128 + gcol], fmaf(cc[3], scr[128 + gcol + 1], pdB));
                }
                psA += __shfl_xor_sync(FULLM, psA, 1); psA += __shfl_xor_sync(FULLM, psA, 2);
                pdA += __shfl_xor_sync(FULLM, pdA, 1); pdA += __shfl_xor_sync(FULLM, pdA, 2);
                psB += __shfl_xor_sync(FULLM, psB, 1); psB += __shfl_xor_sync(FULLM, psB, 2);
                pdB += __shfl_xor_sync(FULLM, pdB, 1); pdB += __shfl_xor_sync(FULLM, pdB, 2);
                if ((lane & 3) == 0) {
                    ALS[(size_t)row0 * HEADS + head] = psA;
                    ALD[(size_t)row0 * HEADS + head] = pdA;
                    ALS[(size_t)(row0 + 8) * HEADS + head] = psB;
                    ALD[(size_t)(row0 + 8) * HEADS + head] = pdB;
                }
            }
        } else {
            constexpr int PT = 132;
            float* T = (float*)smem;    // reuses sAhi+sAlo region (67.6KB <= 69.6KB)
#pragma unroll
            for (int mi = 0; mi < 4; mi++) {
                const int rl = mbase + mi * 16 + gr;
#pragma unroll
                for (int ni = 0; ni < 4; ni++) {
                    const int gcol = nbase + ni * 8 + qc;
                    float* cc = c[mi][ni];
                    float t0 = tanh_fast(cc[0] + scr[gcol]);
                    float t1 = tanh_fast(cc[1] + scr[gcol + 1]);
                    float t2 = tanh_fast(cc[2] + scr[gcol]);
                    float t3 = tanh_fast(cc[3] + scr[gcol + 1]);
                    *(float2*)&T[rl * PT + gcol] = make_float2(t0, t1);
                    *(float2*)&T[(rl + 8) * PT + gcol] = make_float2(t2, t3);
                }
            }
            __syncthreads();
            {
                const int row  = t >> 1;
                const int half = t & 1;
                float acc[8];
#pragma unroll
                for (int o = 0; o < 8; o++) acc[o] = 0.f;
                const float* Tr = T + row * PT + half * 64;
                const float* W2s = scr + 128;
#pragma unroll 4
                for (int k = 0; k < 64; k++) {
                    float tv = Tr[k];
                    const float* w = W2s + (half * 64 + k) * 8;
                    float4 wa = *(const float4*)w;
                    float4 wb = *(const float4*)(w + 4);
                    acc[0] = fmaf(tv, wa.x, acc[0]); acc[1] = fmaf(tv, wa.y, acc[1]);
                    acc[2] = fmaf(tv, wa.z, acc[2]); acc[3] = fmaf(tv, wa.w, acc[3]);
                    acc[4] = fmaf(tv, wb.x, acc[4]); acc[5] = fmaf(tv, wb.y, acc[5]);
                    acc[6] = fmaf(tv, wb.z, acc[6]); acc[7] = fmaf(tv, wb.w, acc[7]);
                }
#pragma unroll
                for (int o = 0; o < 8; o++) acc[o] += __shfl_xor_sync(FULLM, acc[o], 1);
                if (half == 0) {
                    float4 oa = make_float4(acc[0] + bm2[0], acc[1] + bm2[1],
                                            acc[2] + bm2[2], acc[3] + bm2[3]);
                    float4 ob = make_float4(acc[4] + bm2[4], acc[5] + bm2[5],
                                            acc[6] + bm2[6], acc[7] + bm2[7]);
                    *(float4*)&OUT[(size_t)(r0 + row) * DOUT + 0] = oa;
                    *(float4*)&OUT[(size_t)(r0 + row) * DOUT + 4] = ob;
                }
            }
        }
        __syncthreads();   // protect sA (and T) before next tile's convert
    }
}

// =====================================================================
// GAT aggregate — warp-per-node (measured best), uint8 adjacency.
// =====================================================================
__global__ __launch_bounds__(256) void gat_aggregate(
    const float* __restrict__ H, const float* __restrict__ ALS,
    const float* __restrict__ ALD,
    const float* __restrict__ bias, float* __restrict__ Xout)
{
    const int j    = (blockIdx.x * blockDim.x + threadIdx.x) >> 5;
    const int lane = threadIdx.x & 31;
    const int base = (j >> 8) << 8;

    const int d = g_rdeg[j];
    const uint8_t* adj = g_adj8 + (size_t)j * CAP;
    int n0 = (lane < d)      ? base + (int)adj[lane]      : -1;
    int n1 = (lane + 32 < d) ? base + (int)adj[lane + 32] : -1;

    const float4 aldj = *(const float4*)&ALD[(size_t)j * HEADS];

    float e00 = -3.0e38f, e01 = -3.0e38f, e02 = -3.0e38f, e03 = -3.0e38f;
    float e10 = -3.0e38f, e11 = -3.0e38f, e12 = -3.0e38f, e13 = -3.0e38f;
    if (n0 >= 0) {
        float4 s = *(const float4*)&ALS[(size_t)n0 * HEADS];
        e00 = lrelu(s.x + aldj.x); e01 = lrelu(s.y + aldj.y);
        e02 = lrelu(s.z + aldj.z); e03 = lrelu(s.w + aldj.w);
    }
    if (n1 >= 0) {
        float4 s = *(const float4*)&ALS[(size_t)n1 * HEADS];
        e10 = lrelu(s.x + aldj.x); e11 = lrelu(s.y + aldj.y);
        e12 = lrelu(s.z + aldj.z); e13 = lrelu(s.w + aldj.w);
    }

    float a00, a01, a02, a03, a10, a11, a12, a13;
#define SOFTMAX_HEAD(E0, E1, A0, A1)                                        \
    {                                                                       \
        float m = fmaxf(E0, E1);                                            \
        for (int o = 16; o; o >>= 1) m = fmaxf(m, __shfl_xor_sync(FULLM, m, o)); \
        float p0 = (n0 >= 0) ? __expf(E0 - m) : 0.f;                        \
        float p1 = (n1 >= 0) ? __expf(E1 - m) : 0.f;                        \
        float s = p0 + p1;                                                  \
        for (int o = 16; o; o >>= 1) s += __shfl_xor_sync(FULLM, s, o);     \
        float inv = 1.f / (s + 1e-16f);                                     \
        A0 = p0 * inv; A1 = p1 * inv;                                       \
    }
    SOFTMAX_HEAD(e00, e10, a00, a10)
    SOFTMAX_HEAD(e01, e11, a01, a11)
    SOFTMAX_HEAD(e02, e12, a02, a12)
    SOFTMAX_HEAD(e03, e13, a03, a13)
#undef SOFTMAX_HEAD

    float acc0 = 0.f, acc1 = 0.f, acc2 = 0.f, acc3 = 0.f;
    const int dlo = (d < 32) ? d : 32;
    for (int e = 0; e < dlo; e++) {
        int   i  = __shfl_sync(FULLM, n0,  e);
        float w0 = __shfl_sync(FULLM, a00, e);
        float w1 = __shfl_sync(FULLM, a01, e);
        float w2 = __shfl_sync(FULLM, a02, e);
        float w3 = __shfl_sync(FULLM, a03, e);
        const float* hp = H + (size_t)i * HID + lane;
        acc0 = fmaf(w0, __ldg(hp +  0), acc0);
        acc1 = fmaf(w1, __ldg(hp + 32), acc1);
        acc2 = fmaf(w2, __ldg(hp + 64), acc2);
        acc3 = fmaf(w3, __ldg(hp + 96), acc3);
    }
    for (int e = 32; e < d; e++) {
        int   i  = __shfl_sync(FULLM, n1,  e - 32);
        float w0 = __shfl_sync(FULLM, a10, e - 32);
        float w1 = __shfl_sync(FULLM, a11, e - 32);
        float w2 = __shfl_sync(FULLM, a12, e - 32);
        float w3 = __shfl_sync(FULLM, a13, e - 32);
        const float* hp = H + (size_t)i * HID + lane;
        acc0 = fmaf(w0, __ldg(hp +  0), acc0);
        acc1 = fmaf(w1, __ldg(hp + 32), acc1);
        acc2 = fmaf(w2, __ldg(hp + 64), acc2);
        acc3 = fmaf(w3, __ldg(hp + 96), acc3);
    }

    float* xp = Xout + (size_t)j * HID + lane;
    xp[ 0] = fmaxf(acc0 + bias[lane +  0], 0.f);
    xp[32] = fmaxf(acc1 + bias[lane + 32], 0.f);
    xp[64] = fmaxf(acc2 + bias[lane + 64], 0.f);
    xp[96] = fmaxf(acc3 + bias[lane + 96], 0.f);
}

// =====================================================================
// Launcher
// =====================================================================
extern "C" void kernel_launch(void* const* d_in, const int* in_sizes, int n_in,
                              void* d_out, int out_size)
{
    const float* obs    = (const float*)d_in[0];
    const float* W1     = (const float*)d_in[1];
    const float* a1_src = (const float*)d_in[2];
    const float* a1_dst = (const float*)d_in[3];
    const float* b1     = (const float*)d_in[4];
    const float* W2     = (const float*)d_in[5];
    const float* a2_src = (const float*)d_in[6];
    const float* a2_dst = (const float*)d_in[7];
    const float* b2     = (const float*)d_in[8];
    const float* Wm1    = (const float*)d_in[9];
    const float* bm1    = (const float*)d_in[10];
    const float* Wm2    = (const float*)d_in[11];
    const float* bm2    = (const float*)d_in[12];
    float* out = (float*)d_out;

    float* hbuf; cudaGetSymbolAddress((void**)&hbuf, g_hbuf);
    float* xbuf; cudaGetSymbolAddress((void**)&xbuf, g_xbuf);
    float* als;  cudaGetSymbolAddress((void**)&als,  g_als);
    float* ald;  cudaGetSymbolAddress((void**)&ald,  g_ald);
    __nv_bfloat16 *w1h, *w1l, *w2h, *w2l, *wm1h, *wm1l;
    cudaGetSymbolAddress((void**)&w1h,  g_w1_hi);
    cudaGetSymbolAddress((void**)&w1l,  g_w1_lo);
    cudaGetSymbolAddress((void**)&w2h,  g_w2_hi);
    cudaGetSymbolAddress((void**)&w2l,  g_w2_lo);
    cudaGetSymbolAddress((void**)&wm1h, g_wm1_hi);
    cudaGetSymbolAddress((void**)&wm1l, g_wm1_lo);

    const int SMEM32  = 4 * 128 * (DIN + 8) * 2 + 8 * 1024;
    const int SMEM128 = 4 * 128 * (HID + 8) * 2 + 8 * 1024;
    cudaFuncSetAttribute(mma_gemm<DIN, 0>, cudaFuncAttributeMaxDynamicSharedMemorySize, SMEM32);
    cudaFuncSetAttribute(mma_gemm<HID, 0>, cudaFuncAttributeMaxDynamicSharedMemorySize, SMEM128);
    cudaFuncSetAttribute(mma_gemm<HID, 1>, cudaFuncAttributeMaxDynamicSharedMemorySize, SMEM128);

    const int NSM      = 148;
    const int GRID32   = 2 * NSM;   // 2 CTAs/SM fit for K=32 (49KB smem)
    const int GRID128  = NSM;       // 1 CTA/SM (147KB smem)
    const int AGG_BLOCKS = NODES / 8;

    prep_w_kernel<<<(DIN * 128 + 255) / 256, 256>>>(W1,  DIN, w1h,  w1l);
    prep_w_kernel<<<(HID * 128 + 255) / 256, 256>>>(W2,  HID, w2h,  w2l);
    prep_w_kernel<<<(HID * 128 + 255) / 256, 256>>>(Wm1, HID, wm1h, wm1l);

    knn_kernel<<<Bsz, 512>>>(obs);

    mma_gemm<DIN, 0><<<GRID32, 256, SMEM32>>>(obs, w1h, w1l, a1_src, a1_dst,
        nullptr, nullptr, nullptr, hbuf, als, ald, nullptr);
    gat_aggregate<<<AGG_BLOCKS, 256>>>(hbuf, als, ald, b1, xbuf);

    mma_gemm<HID, 0><<<GRID128, 256, SMEM128>>>(xbuf, w2h, w2l, a2_src, a2_dst,
        nullptr, nullptr, nullptr, hbuf, als, ald, nullptr);
    gat_aggregate<<<AGG_BLOCKS, 256>>>(hbuf, als, ald, b2, xbuf);

    mma_gemm<HID, 1><<<GRID128, 256, SMEM128>>>(xbuf, wm1h, wm1l, nullptr, nullptr,
        bm1, Wm2, bm2, nullptr, nullptr, nullptr, out);
}

// round 12
// speedup vs baseline: 1.3346x; 1.0309x over previous
#include <cuda_runtime.h>
#include <cuda_bf16.h>
#include <cuda_fp16.h>
#include <cstdint>
#include <math.h>

#define Bsz   512
#define Nn    256
#define NODES (Bsz * Nn)      // 131072
#define DIN   32
#define HID   128
#define HEADS 4
#define Knn   5
#define DOUT  8
#define CAP   40
#define NEG_SLOPE 0.2f
#define FULLM 0xffffffffu
#define NTILES (NODES / 128)  // 1024

// ---------------- static device scratch ----------------
__device__ int     g_rdeg[NODES];
__device__ uint8_t g_adj8[(size_t)NODES * CAP];     // local (in-batch) indices
__device__ __half  g_hbuf[(size_t)NODES * HID];     // fp16 H (gathered by aggregate)
__device__ float   g_xbuf[(size_t)NODES * HID];
__device__ float   g_als[(size_t)NODES * HEADS];
__device__ float   g_ald[(size_t)NODES * HEADS];
// bf16 hi/lo images of W^T: [n=128 rows][k] row-major
__device__ __nv_bfloat16 g_w1_hi[128 * DIN],  g_w1_lo[128 * DIN];
__device__ __nv_bfloat16 g_w2_hi[128 * HID],  g_w2_lo[128 * HID];
__device__ __nv_bfloat16 g_wm1_hi[128 * HID], g_wm1_lo[128 * HID];

__device__ __forceinline__ float tanh_fast(float x) {
    return __fdividef(2.f, 1.f + __expf(-2.f * x)) - 1.f;
}
__device__ __forceinline__ float lrelu(float v) {
    return (v > 0.f) ? v : NEG_SLOPE * v;
}
__device__ __forceinline__ uint32_t smem_u32(const void* p) {
    uint32_t a;
    asm("{ .reg .u64 t; cvta.to.shared.u64 t, %1; cvt.u32.u64 %0, t; }" : "=r"(a) : "l"(p));
    return a;
}
__device__ __forceinline__ void ldsm_x4(uint32_t* r, uint32_t addr) {
    asm volatile("ldmatrix.sync.aligned.m8n8.x4.shared.b16 {%0,%1,%2,%3}, [%4];"
                 : "=r"(r[0]), "=r"(r[1]), "=r"(r[2]), "=r"(r[3]) : "r"(addr));
}
__device__ __forceinline__ void ldsm_x2(uint32_t* r, uint32_t addr) {
    asm volatile("ldmatrix.sync.aligned.m8n8.x2.shared.b16 {%0,%1}, [%2];"
                 : "=r"(r[0]), "=r"(r[1]) : "r"(addr));
}
__device__ __forceinline__ void mma_bf16(float* c, const uint32_t* a, const uint32_t* b) {
    asm volatile("mma.sync.aligned.m16n8k16.row.col.f32.bf16.bf16.f32 "
                 "{%0,%1,%2,%3}, {%4,%5,%6,%7}, {%8,%9}, {%0,%1,%2,%3};"
                 : "+f"(c[0]), "+f"(c[1]), "+f"(c[2]), "+f"(c[3])
                 : "r"(a[0]), "r"(a[1]), "r"(a[2]), "r"(a[3]), "r"(b[0]), "r"(b[1]));
}
__device__ __forceinline__ uint32_t pack_bf2(__nv_bfloat16 a, __nv_bfloat16 b) {
    return (uint32_t)__bfloat16_as_ushort(a) | ((uint32_t)__bfloat16_as_ushort(b) << 16);
}

// =====================================================================
// Prep: W [K,128] -> hi/lo bf16 images of W^T [128][K]
// =====================================================================
__global__ void prep_w_kernel(const float* __restrict__ W, int K,
                              __nv_bfloat16* __restrict__ hi, __nv_bfloat16* __restrict__ lo)
{
    int idx = blockIdx.x * blockDim.x + threadIdx.x;
    if (idx >= K * 128) return;
    int k = idx >> 7, n = idx & 127;
    float x = W[idx];
    __nv_bfloat16 h = __float2bfloat16(x);
    __nv_bfloat16 l = __float2bfloat16(x - __bfloat162float(h));
    hi[n * K + k] = h;
    lo[n * K + k] = l;
}

// =====================================================================
// KNN v2 (measured 55 us): block per batch, 512 threads.
// =====================================================================
__global__ __launch_bounds__(512) void knn_kernel(const float* __restrict__ obs)
{
    __shared__ float   sx[Nn];
    __shared__ float   sy[Nn];
    __shared__ int     sdeg[Nn];
    __shared__ uint8_t sadj[Nn * CAP];
    __shared__ float   mbd[Nn * 2 * Knn];
    __shared__ int     mbi[Nn * 2 * Knn];

    const int b = blockIdx.x;
    const int t = threadIdx.x;
    const int n = t & (Nn - 1);
    const int half = t >> 8;

    if (t < Nn) {
        const size_t base = ((size_t)b * Nn + n) * DIN;
        sx[n] = obs[base + 0];
        sy[n] = obs[base + 1];
        sdeg[n] = 1;
        sadj[n * CAP + 0] = (uint8_t)n;
    }
    __syncthreads();

    const float px = sx[n], py = sy[n];
    float bd[Knn];
    int   bi[Knn];
#pragma unroll
    for (int s = 0; s < Knn; s++) { bd[s] = 3.0e38f; bi[s] = -1; }

    const int j0 = half * 128;
    for (int jj = 0; jj < 128; jj++) {
        const int j = j0 + jj;
        float dx = sx[j] - px;
        float dy = sy[j] - py;
        float d  = fmaf(dx, dx, dy * dy);
        if (j == n) d = 3.0e38f;
        if (d < bd[Knn - 1]) {
            bd[Knn - 1] = d; bi[Knn - 1] = j;
#pragma unroll
            for (int s = Knn - 2; s >= 0; s--) {
                if (bd[s + 1] < bd[s]) {
                    float td = bd[s]; bd[s] = bd[s + 1]; bd[s + 1] = td;
                    int   ti = bi[s]; bi[s] = bi[s + 1]; bi[s + 1] = ti;
                }
            }
        }
    }
#pragma unroll
    for (int s = 0; s < Knn; s++) {
        mbd[(n * 2 + half) * Knn + s] = bd[s];
        mbi[(n * 2 + half) * Knn + s] = bi[s];
    }
    __syncthreads();

    if (t < Nn) {
        const float* A  = &mbd[(n * 2 + 0) * Knn];
        const float* B  = &mbd[(n * 2 + 1) * Knn];
        const int*   Ai = &mbi[(n * 2 + 0) * Knn];
        const int*   Bi = &mbi[(n * 2 + 1) * Knn];
        int ia = 0, ib = 0;
#pragma unroll
        for (int s = 0; s < Knn; s++) {
            int jn;
            if (A[ia] <= B[ib]) jn = Ai[ia++];
            else                jn = Bi[ib++];
            int p = atomicAdd(&sdeg[jn], 1);
            if (p < CAP) sadj[jn * CAP + p] = (uint8_t)n;
        }
    }
    __syncthreads();

    if (t < Nn) {
        int deg = min(sdeg[n], CAP);
        g_rdeg[b * Nn + n] = deg;
        uint8_t* dst = g_adj8 + (size_t)(b * Nn + n) * CAP;
        const uint32_t* srcw = (const uint32_t*)&sadj[n * CAP];
#pragma unroll
        for (int w = 0; w < CAP / 4; w++)
            ((uint32_t*)dst)[w] = srcw[w];
    }
}

// =====================================================================
// PERSISTENT mma.sync GEMM. MODE0 now stores H as fp16 (half2 stores).
// =====================================================================
template<int KDIM, int MODE>
__global__ __launch_bounds__(256) void mma_gemm(
    const float* __restrict__ X,
    const __nv_bfloat16* __restrict__ gBhi, const __nv_bfloat16* __restrict__ gBlo,
    const float* __restrict__ asrc, const float* __restrict__ adst,
    const float* __restrict__ bias, const float* __restrict__ Wm2,
    const float* __restrict__ bm2,
    __half* __restrict__ H, float* __restrict__ ALS, float* __restrict__ ALD,
    float* __restrict__ OUT)
{
    constexpr int PK = KDIM + 8;
    extern __shared__ __align__(16) char smem[];
    __nv_bfloat16* sAhi = (__nv_bfloat16*)smem;
    __nv_bfloat16* sAlo = sAhi + 128 * PK;
    __nv_bfloat16* sBhi = sAlo + 128 * PK;
    __nv_bfloat16* sBlo = sBhi + 128 * PK;
    float* scr = (float*)(sBlo + 128 * PK);

    const int t = threadIdx.x, wid = t >> 5, lane = t & 31;

    if (MODE == 0) {
        if (t < 128) { scr[t] = asrc[t]; scr[128 + t] = adst[t]; }
    } else {
        if (t < 128) scr[t] = bias[t];
        for (int e = t; e < 1024; e += 256) scr[128 + e] = Wm2[e];
    }
    for (int idx = t; idx < 128 * (KDIM / 8); idx += 256) {
        int n  = idx / (KDIM / 8);
        int kc = (idx % (KDIM / 8)) * 8;
        *(float4*)&sBhi[n * PK + kc] = *(const float4*)&gBhi[n * KDIM + kc];
        *(float4*)&sBlo[n * PK + kc] = *(const float4*)&gBlo[n * KDIM + kc];
    }
    __syncthreads();

    const int mbase = (wid & 1) * 64;
    const int nbase = (wid >> 1) * 32;
    const int arow = mbase + (lane & 7) + ((lane >> 3) & 1) * 8;
    const int ak   = (lane >> 4) * 8;
    const int brow = nbase + (lane & 7);
    const int bk   = ((lane >> 3) & 1) * 8;
    const int gr = lane >> 2;
    const int qc = (lane & 3) * 2;

    for (int tile = blockIdx.x; tile < NTILES; tile += gridDim.x) {
        const int r0 = tile * 128;

        for (int idx = t; idx < 128 * (KDIM / 2); idx += 256) {
            int row = idx / (KDIM / 2);
            int k   = (idx % (KDIM / 2)) * 2;
            float2 v = *(const float2*)&X[(size_t)(r0 + row) * KDIM + k];
            __nv_bfloat16 h0 = __float2bfloat16(v.x);
            __nv_bfloat16 h1 = __float2bfloat16(v.y);
            __nv_bfloat16 l0 = __float2bfloat16(v.x - __bfloat162float(h0));
            __nv_bfloat16 l1 = __float2bfloat16(v.y - __bfloat162float(h1));
            *(uint32_t*)&sAhi[row * PK + k] = pack_bf2(h0, h1);
            *(uint32_t*)&sAlo[row * PK + k] = pack_bf2(l0, l1);
        }
        __syncthreads();

        float c[4][4][4];
#pragma unroll
        for (int mi = 0; mi < 4; mi++)
#pragma unroll
            for (int ni = 0; ni < 4; ni++)
#pragma unroll
                for (int q = 0; q < 4; q++) c[mi][ni][q] = 0.f;

#pragma unroll
        for (int p = 0; p < 3; p++) {
            const __nv_bfloat16* A  = (p == 2) ? sAlo : sAhi;
            const __nv_bfloat16* Bm = (p == 1) ? sBlo : sBhi;
#pragma unroll
            for (int ks = 0; ks < KDIM / 16; ks++) {
                uint32_t a[4][4], b[4][2];
#pragma unroll
                for (int mi = 0; mi < 4; mi++)
                    ldsm_x4(a[mi], smem_u32(&A[(arow + mi * 16) * PK + ks * 16 + ak]));
#pragma unroll
                for (int ni = 0; ni < 4; ni++)
                    ldsm_x2(b[ni], smem_u32(&Bm[(brow + ni * 8) * PK + ks * 16 + bk]));
#pragma unroll
                for (int mi = 0; mi < 4; mi++)
#pragma unroll
                    for (int ni = 0; ni < 4; ni++)
                        mma_bf16(c[mi][ni], a[mi], b[ni]);
            }
        }
        __syncthreads();

        if (MODE == 0) {
            const int head = wid >> 1;
#pragma unroll
            for (int mi = 0; mi < 4; mi++) {
                const int row0 = r0 + mbase + mi * 16 + gr;
                float psA = 0.f, pdA = 0.f, psB = 0.f, pdB = 0.f;
#pragma unroll
                for (int ni = 0; ni < 4; ni++) {
                    const int gcol = nbase + ni * 8 + qc;
                    float* cc = c[mi][ni];
                    *(__half2*)&H[(size_t)row0 * HID + gcol] =
                        __floats2half2_rn(cc[0], cc[1]);
                    *(__half2*)&H[(size_t)(row0 + 8) * HID + gcol] =
                        __floats2half2_rn(cc[2], cc[3]);
                    psA = fmaf(cc[0], scr[gcol], fmaf(cc[1], scr[gcol + 1], psA));
                    pdA = fmaf(cc[0], scr[128 + gcol], fmaf(cc[1], scr[128 + gcol + 1], pdA));
                    psB = fmaf(cc[2], scr[gcol], fmaf(cc[3], scr[gcol + 1], psB));
                    pdB = fmaf(cc[2], scr[128 + gcol], fmaf(cc[3], scr[128 + gcol + 1], pdB));
                }
                psA += __shfl_xor_sync(FULLM, psA, 1); psA += __shfl_xor_sync(FULLM, psA, 2);
                pdA += __shfl_xor_sync(FULLM, pdA, 1); pdA += __shfl_xor_sync(FULLM, pdA, 2);
                psB += __shfl_xor_sync(FULLM, psB, 1); psB += __shfl_xor_sync(FULLM, psB, 2);
                pdB += __shfl_xor_sync(FULLM, pdB, 1); pdB += __shfl_xor_sync(FULLM, pdB, 2);
                if ((lane & 3) == 0) {
                    ALS[(size_t)row0 * HEADS + head] = psA;
                    ALD[(size_t)row0 * HEADS + head] = pdA;
                    ALS[(size_t)(row0 + 8) * HEADS + head] = psB;
                    ALD[(size_t)(row0 + 8) * HEADS + head] = pdB;
                }
            }
        } else {
            constexpr int PT = 132;
            float* T = (float*)smem;    // reuses sAhi+sAlo region
#pragma unroll
            for (int mi = 0; mi < 4; mi++) {
                const int rl = mbase + mi * 16 + gr;
#pragma unroll
                for (int ni = 0; ni < 4; ni++) {
                    const int gcol = nbase + ni * 8 + qc;
                    float* cc = c[mi][ni];
                    float t0 = tanh_fast(cc[0] + scr[gcol]);
                    float t1 = tanh_fast(cc[1] + scr[gcol + 1]);
                    float t2 = tanh_fast(cc[2] + scr[gcol]);
                    float t3 = tanh_fast(cc[3] + scr[gcol + 1]);
                    *(float2*)&T[rl * PT + gcol] = make_float2(t0, t1);
                    *(float2*)&T[(rl + 8) * PT + gcol] = make_float2(t2, t3);
                }
            }
            __syncthreads();
            {
                const int row  = t >> 1;
                const int half = t & 1;
                float acc[8];
#pragma unroll
                for (int o = 0; o < 8; o++) acc[o] = 0.f;
                const float* Tr = T + row * PT + half * 64;
                const float* W2s = scr + 128;
#pragma unroll 4
                for (int k = 0; k < 64; k++) {
                    float tv = Tr[k];
                    const float* w = W2s + (half * 64 + k) * 8;
                    float4 wa = *(const float4*)w;
                    float4 wb = *(const float4*)(w + 4);
                    acc[0] = fmaf(tv, wa.x, acc[0]); acc[1] = fmaf(tv, wa.y, acc[1]);
                    acc[2] = fmaf(tv, wa.z, acc[2]); acc[3] = fmaf(tv, wa.w, acc[3]);
                    acc[4] = fmaf(tv, wb.x, acc[4]); acc[5] = fmaf(tv, wb.y, acc[5]);
                    acc[6] = fmaf(tv, wb.z, acc[6]); acc[7] = fmaf(tv, wb.w, acc[7]);
                }
#pragma unroll
                for (int o = 0; o < 8; o++) acc[o] += __shfl_xor_sync(FULLM, acc[o], 1);
                if (half == 0) {
                    float4 oa = make_float4(acc[0] + bm2[0], acc[1] + bm2[1],
                                            acc[2] + bm2[2], acc[3] + bm2[3]);
                    float4 ob = make_float4(acc[4] + bm2[4], acc[5] + bm2[5],
                                            acc[6] + bm2[6], acc[7] + bm2[7]);
                    *(float4*)&OUT[(size_t)(r0 + row) * DOUT + 0] = oa;
                    *(float4*)&OUT[(size_t)(r0 + row) * DOUT + 4] = ob;
                }
            }
        }
        __syncthreads();
    }
}

// =====================================================================
// GAT aggregate — warp-per-node, uint8 adjacency, fp16 H gathers.
// =====================================================================
__global__ __launch_bounds__(256) void gat_aggregate(
    const __half* __restrict__ H, const float* __restrict__ ALS,
    const float* __restrict__ ALD,
    const float* __restrict__ bias, float* __restrict__ Xout)
{
    const int j    = (blockIdx.x * blockDim.x + threadIdx.x) >> 5;
    const int lane = threadIdx.x & 31;
    const int base = (j >> 8) << 8;

    const int d = g_rdeg[j];
    const uint8_t* adj = g_adj8 + (size_t)j * CAP;
    int n0 = (lane < d)      ? base + (int)adj[lane]      : -1;
    int n1 = (lane + 32 < d) ? base + (int)adj[lane + 32] : -1;

    const float4 aldj = *(const float4*)&ALD[(size_t)j * HEADS];

    float e00 = -3.0e38f, e01 = -3.0e38f, e02 = -3.0e38f, e03 = -3.0e38f;
    float e10 = -3.0e38f, e11 = -3.0e38f, e12 = -3.0e38f, e13 = -3.0e38f;
    if (n0 >= 0) {
        float4 s = *(const float4*)&ALS[(size_t)n0 * HEADS];
        e00 = lrelu(s.x + aldj.x); e01 = lrelu(s.y + aldj.y);
        e02 = lrelu(s.z + aldj.z); e03 = lrelu(s.w + aldj.w);
    }
    if (n1 >= 0) {
        float4 s = *(const float4*)&ALS[(size_t)n1 * HEADS];
        e10 = lrelu(s.x + aldj.x); e11 = lrelu(s.y + aldj.y);
        e12 = lrelu(s.z + aldj.z); e13 = lrelu(s.w + aldj.w);
    }

    float a00, a01, a02, a03, a10, a11, a12, a13;
#define SOFTMAX_HEAD(E0, E1, A0, A1)                                        \
    {                                                                       \
        float m = fmaxf(E0, E1);                                            \
        for (int o = 16; o; o >>= 1) m = fmaxf(m, __shfl_xor_sync(FULLM, m, o)); \
        float p0 = (n0 >= 0) ? __expf(E0 - m) : 0.f;                        \
        float p1 = (n1 >= 0) ? __expf(E1 - m) : 0.f;                        \
        float s = p0 + p1;                                                  \
        for (int o = 16; o; o >>= 1) s += __shfl_xor_sync(FULLM, s, o);     \
        float inv = 1.f / (s + 1e-16f);                                     \
        A0 = p0 * inv; A1 = p1 * inv;                                       \
    }
    SOFTMAX_HEAD(e00, e10, a00, a10)
    SOFTMAX_HEAD(e01, e11, a01, a11)
    SOFTMAX_HEAD(e02, e12, a02, a12)
    SOFTMAX_HEAD(e03, e13, a03, a13)
#undef SOFTMAX_HEAD

    float acc0 = 0.f, acc1 = 0.f, acc2 = 0.f, acc3 = 0.f;
    const int dlo = (d < 32) ? d : 32;
    for (int e = 0; e < dlo; e++) {
        int   i  = __shfl_sync(FULLM, n0,  e);
        float w0 = __shfl_sync(FULLM, a00, e);
        float w1 = __shfl_sync(FULLM, a01, e);
        float w2 = __shfl_sync(FULLM, a02, e);
        float w3 = __shfl_sync(FULLM, a03, e);
        const __half* hp = H + (size_t)i * HID + lane;
        acc0 = fmaf(w0, __half2float(__ldg(hp +  0)), acc0);
        acc1 = fmaf(w1, __half2float(__ldg(hp + 32)), acc1);
        acc2 = fmaf(w2, __half2float(__ldg(hp + 64)), acc2);
        acc3 = fmaf(w3, __half2float(__ldg(hp + 96)), acc3);
    }
    for (int e = 32; e < d; e++) {
        int   i  = __shfl_sync(FULLM, n1,  e - 32);
        float w0 = __shfl_sync(FULLM, a10, e - 32);
        float w1 = __shfl_sync(FULLM, a11, e - 32);
        float w2 = __shfl_sync(FULLM, a12, e - 32);
        float w3 = __shfl_sync(FULLM, a13, e - 32);
        const __half* hp = H + (size_t)i * HID + lane;
        acc0 = fmaf(w0, __half2float(__ldg(hp +  0)), acc0);
        acc1 = fmaf(w1, __half2float(__ldg(hp + 32)), acc1);
        acc2 = fmaf(w2, __half2float(__ldg(hp + 64)), acc2);
        acc3 = fmaf(w3, __half2float(__ldg(hp + 96)), acc3);
    }

    float* xp = Xout + (size_t)j * HID + lane;
    xp[ 0] = fmaxf(acc0 + bias[lane +  0], 0.f);
    xp[32] = fmaxf(acc1 + bias[lane + 32], 0.f);
    xp[64] = fmaxf(acc2 + bias[lane + 64], 0.f);
    xp[96] = fmaxf(acc3 + bias[lane + 96], 0.f);
}

// =====================================================================
// Launcher
// =====================================================================
extern "C" void kernel_launch(void* const* d_in, const int* in_sizes, int n_in,
                              void* d_out, int out_size)
{
    const float* obs    = (const float*)d_in[0];
    const float* W1     = (const float*)d_in[1];
    const float* a1_src = (const float*)d_in[2];
    const float* a1_dst = (const float*)d_in[3];
    const float* b1     = (const float*)d_in[4];
    const float* W2     = (const float*)d_in[5];
    const float* a2_src = (const float*)d_in[6];
    const float* a2_dst = (const float*)d_in[7];
    const float* b2     = (const float*)d_in[8];
    const float* Wm1    = (const float*)d_in[9];
    const float* bm1    = (const float*)d_in[10];
    const float* Wm2    = (const float*)d_in[11];
    const float* bm2    = (const float*)d_in[12];
    float* out = (float*)d_out;

    __half* hbuf; cudaGetSymbolAddress((void**)&hbuf, g_hbuf);
    float* xbuf; cudaGetSymbolAddress((void**)&xbuf, g_xbuf);
    float* als;  cudaGetSymbolAddress((void**)&als,  g_als);
    float* ald;  cudaGetSymbolAddress((void**)&ald,  g_ald);
    __nv_bfloat16 *w1h, *w1l, *w2h, *w2l, *wm1h, *wm1l;
    cudaGetSymbolAddress((void**)&w1h,  g_w1_hi);
    cudaGetSymbolAddress((void**)&w1l,  g_w1_lo);
    cudaGetSymbolAddress((void**)&w2h,  g_w2_hi);
    cudaGetSymbolAddress((void**)&w2l,  g_w2_lo);
    cudaGetSymbolAddress((void**)&wm1h, g_wm1_hi);
    cudaGetSymbolAddress((void**)&wm1l, g_wm1_lo);

    const int SMEM32  = 4 * 128 * (DIN + 8) * 2 + 8 * 1024;
    const int SMEM128 = 4 * 128 * (HID + 8) * 2 + 8 * 1024;
    cudaFuncSetAttribute(mma_gemm<DIN, 0>, cudaFuncAttributeMaxDynamicSharedMemorySize, SMEM32);
    cudaFuncSetAttribute(mma_gemm<HID, 0>, cudaFuncAttributeMaxDynamicSharedMemorySize, SMEM128);
    cudaFuncSetAttribute(mma_gemm<HID, 1>, cudaFuncAttributeMaxDynamicSharedMemorySize, SMEM128);

    const int NSM      = 148;
    const int GRID32   = 2 * NSM;
    const int GRID128  = NSM;
    const int AGG_BLOCKS = NODES / 8;

    prep_w_kernel<<<(DIN * 128 + 255) / 256, 256>>>(W1,  DIN, w1h,  w1l);
    prep_w_kernel<<<(HID * 128 + 255) / 256, 256>>>(W2,  HID, w2h,  w2l);
    prep_w_kernel<<<(HID * 128 + 255) / 256, 256>>>(Wm1, HID, wm1h, wm1l);

    knn_kernel<<<Bsz, 512>>>(obs);

    mma_gemm<DIN, 0><<<GRID32, 256, SMEM32>>>(obs, w1h, w1l, a1_src, a1_dst,
        nullptr, nullptr, nullptr, hbuf, als, ald, nullptr);
    gat_aggregate<<<AGG_BLOCKS, 256>>>(hbuf, als, ald, b1, xbuf);

    mma_gemm<HID, 0><<<GRID128, 256, SMEM128>>>(xbuf, w2h, w2l, a2_src, a2_dst,
        nullptr, nullptr, nullptr, hbuf, als, ald, nullptr);
    gat_aggregate<<<AGG_BLOCKS, 256>>>(hbuf, als, ald, b2, xbuf);

    mma_gemm<HID, 1><<<GRID128, 256, SMEM128>>>(xbuf, wm1h, wm1l, nullptr, nullptr,
        bm1, Wm2, bm2, nullptr, nullptr, nullptr, out);
}

// round 13
// speedup vs baseline: 1.3947x; 1.0451x over previous
#include <cuda_runtime.h>
#include <cuda_bf16.h>
#include <cuda_fp16.h>
#include <cstdint>
#include <math.h>

#define Bsz   512
#define Nn    256
#define NODES (Bsz * Nn)      // 131072
#define DIN   32
#define HID   128
#define HEADS 4
#define Knn   5
#define DOUT  8
#define CAP   40
#define NEG_SLOPE 0.2f
#define FULLM 0xffffffffu
#define NTILES (NODES / 128)  // 1024

// ---------------- static device scratch ----------------
__device__ int     g_rdeg[NODES];
__device__ uint8_t g_adj8[(size_t)NODES * CAP];     // local (in-batch) indices
__device__ __half  g_hbuf[(size_t)NODES * HID];     // fp16 H (gathered by aggregate)
__device__ float   g_xbuf[(size_t)NODES * HID];
__device__ float   g_als[(size_t)NODES * HEADS];
__device__ float   g_ald[(size_t)NODES * HEADS];
// bf16 hi/lo images of W^T: [n=128 rows][k] row-major
__device__ __nv_bfloat16 g_w1_hi[128 * DIN],  g_w1_lo[128 * DIN];
__device__ __nv_bfloat16 g_w2_hi[128 * HID],  g_w2_lo[128 * HID];
__device__ __nv_bfloat16 g_wm1_hi[128 * HID], g_wm1_lo[128 * HID];

__device__ __forceinline__ float tanh_fast(float x) {
    return __fdividef(2.f, 1.f + __expf(-2.f * x)) - 1.f;
}
__device__ __forceinline__ float lrelu(float v) {
    return (v > 0.f) ? v : NEG_SLOPE * v;
}
__device__ __forceinline__ uint32_t smem_u32(const void* p) {
    uint32_t a;
    asm("{ .reg .u64 t; cvta.to.shared.u64 t, %1; cvt.u32.u64 %0, t; }" : "=r"(a) : "l"(p));
    return a;
}
__device__ __forceinline__ void ldsm_x4(uint32_t* r, uint32_t addr) {
    asm volatile("ldmatrix.sync.aligned.m8n8.x4.shared.b16 {%0,%1,%2,%3}, [%4];"
                 : "=r"(r[0]), "=r"(r[1]), "=r"(r[2]), "=r"(r[3]) : "r"(addr));
}
__device__ __forceinline__ void ldsm_x2(uint32_t* r, uint32_t addr) {
    asm volatile("ldmatrix.sync.aligned.m8n8.x2.shared.b16 {%0,%1}, [%2];"
                 : "=r"(r[0]), "=r"(r[1]) : "r"(addr));
}
__device__ __forceinline__ void mma_bf16(float* c, const uint32_t* a, const uint32_t* b) {
    asm volatile("mma.sync.aligned.m16n8k16.row.col.f32.bf16.bf16.f32 "
                 "{%0,%1,%2,%3}, {%4,%5,%6,%7}, {%8,%9}, {%0,%1,%2,%3};"
                 : "+f"(c[0]), "+f"(c[1]), "+f"(c[2]), "+f"(c[3])
                 : "r"(a[0]), "r"(a[1]), "r"(a[2]), "r"(a[3]), "r"(b[0]), "r"(b[1]));
}
__device__ __forceinline__ uint32_t pack_bf2(__nv_bfloat16 a, __nv_bfloat16 b) {
    return (uint32_t)__bfloat16_as_ushort(a) | ((uint32_t)__bfloat16_as_ushort(b) << 16);
}

// =====================================================================
// Prep: W [K,128] -> hi/lo bf16 images of W^T [128][K]
// =====================================================================
__global__ void prep_w_kernel(const float* __restrict__ W, int K,
                              __nv_bfloat16* __restrict__ hi, __nv_bfloat16* __restrict__ lo)
{
    int idx = blockIdx.x * blockDim.x + threadIdx.x;
    if (idx >= K * 128) return;
    int k = idx >> 7, n = idx & 127;
    float x = W[idx];
    __nv_bfloat16 h = __float2bfloat16(x);
    __nv_bfloat16 l = __float2bfloat16(x - __bfloat162float(h));
    hi[n * K + k] = h;
    lo[n * K + k] = l;
}

// =====================================================================
// KNN v2 (measured 55 us): block per batch, 512 threads.
// =====================================================================
__global__ __launch_bounds__(512) void knn_kernel(const float* __restrict__ obs)
{
    __shared__ float   sx[Nn];
    __shared__ float   sy[Nn];
    __shared__ int     sdeg[Nn];
    __shared__ uint8_t sadj[Nn * CAP];
    __shared__ float   mbd[Nn * 2 * Knn];
    __shared__ int     mbi[Nn * 2 * Knn];

    const int b = blockIdx.x;
    const int t = threadIdx.x;
    const int n = t & (Nn - 1);
    const int half = t >> 8;

    if (t < Nn) {
        const size_t base = ((size_t)b * Nn + n) * DIN;
        sx[n] = obs[base + 0];
        sy[n] = obs[base + 1];
        sdeg[n] = 1;
        sadj[n * CAP + 0] = (uint8_t)n;
    }
    __syncthreads();

    const float px = sx[n], py = sy[n];
    float bd[Knn];
    int   bi[Knn];
#pragma unroll
    for (int s = 0; s < Knn; s++) { bd[s] = 3.0e38f; bi[s] = -1; }

    const int j0 = half * 128;
    for (int jj = 0; jj < 128; jj++) {
        const int j = j0 + jj;
        float dx = sx[j] - px;
        float dy = sy[j] - py;
        float d  = fmaf(dx, dx, dy * dy);
        if (j == n) d = 3.0e38f;
        if (d < bd[Knn - 1]) {
            bd[Knn - 1] = d; bi[Knn - 1] = j;
#pragma unroll
            for (int s = Knn - 2; s >= 0; s--) {
                if (bd[s + 1] < bd[s]) {
                    float td = bd[s]; bd[s] = bd[s + 1]; bd[s + 1] = td;
                    int   ti = bi[s]; bi[s] = bi[s + 1]; bi[s + 1] = ti;
                }
            }
        }
    }
#pragma unroll
    for (int s = 0; s < Knn; s++) {
        mbd[(n * 2 + half) * Knn + s] = bd[s];
        mbi[(n * 2 + half) * Knn + s] = bi[s];
    }
    __syncthreads();

    if (t < Nn) {
        const float* A  = &mbd[(n * 2 + 0) * Knn];
        const float* B  = &mbd[(n * 2 + 1) * Knn];
        const int*   Ai = &mbi[(n * 2 + 0) * Knn];
        const int*   Bi = &mbi[(n * 2 + 1) * Knn];
        int ia = 0, ib = 0;
#pragma unroll
        for (int s = 0; s < Knn; s++) {
            int jn;
            if (A[ia] <= B[ib]) jn = Ai[ia++];
            else                jn = Bi[ib++];
            int p = atomicAdd(&sdeg[jn], 1);
            if (p < CAP) sadj[jn * CAP + p] = (uint8_t)n;
        }
    }
    __syncthreads();

    if (t < Nn) {
        int deg = min(sdeg[n], CAP);
        g_rdeg[b * Nn + n] = deg;
        uint8_t* dst = g_adj8 + (size_t)(b * Nn + n) * CAP;
        const uint32_t* srcw = (const uint32_t*)&sadj[n * CAP];
#pragma unroll
        for (int w = 0; w < CAP / 4; w++)
            ((uint32_t*)dst)[w] = srcw[w];
    }
}

// =====================================================================
// PERSISTENT mma.sync GEMM, 3-tile smem (sAhi, sAlo, shared sB) for
// 2 CTAs/SM. Passes: Ah*Bh, Al*Bh (Bh resident) then swap B -> Ah*Bl.
// =====================================================================
template<int KDIM, int MODE>
__global__ __launch_bounds__(256, 2) void mma_gemm(
    const float* __restrict__ X,
    const __nv_bfloat16* __restrict__ gBhi, const __nv_bfloat16* __restrict__ gBlo,
    const float* __restrict__ asrc, const float* __restrict__ adst,
    const float* __restrict__ bias, const float* __restrict__ Wm2,
    const float* __restrict__ bm2,
    __half* __restrict__ H, float* __restrict__ ALS, float* __restrict__ ALD,
    float* __restrict__ OUT)
{
    constexpr int PK = KDIM + 8;
    extern __shared__ __align__(16) char smem[];
    __nv_bfloat16* sAhi = (__nv_bfloat16*)smem;
    __nv_bfloat16* sAlo = sAhi + 128 * PK;
    __nv_bfloat16* sB   = sAlo + 128 * PK;
    float* scr = (float*)(sB + 128 * PK);

    const int t = threadIdx.x, wid = t >> 5, lane = t & 31;

    if (MODE == 0) {
        if (t < 128) { scr[t] = asrc[t]; scr[128 + t] = adst[t]; }
    } else {
        if (t < 128) scr[t] = bias[t];
        for (int e = t; e < 1024; e += 256) scr[128 + e] = Wm2[e];
    }
    __syncthreads();

    const int mbase = (wid & 1) * 64;
    const int nbase = (wid >> 1) * 32;
    const int arow = mbase + (lane & 7) + ((lane >> 3) & 1) * 8;
    const int ak   = (lane >> 4) * 8;
    const int brow = nbase + (lane & 7);
    const int bk   = ((lane >> 3) & 1) * 8;
    const int gr = lane >> 2;
    const int qc = (lane & 3) * 2;

    for (int tile = blockIdx.x; tile < NTILES; tile += gridDim.x) {
        const int r0 = tile * 128;

        // ---- convert X tile -> sAhi/sAlo ; copy Bhi -> sB ----
        for (int idx = t; idx < 128 * (KDIM / 2); idx += 256) {
            int row = idx / (KDIM / 2);
            int k   = (idx % (KDIM / 2)) * 2;
            float2 v = *(const float2*)&X[(size_t)(r0 + row) * KDIM + k];
            __nv_bfloat16 h0 = __float2bfloat16(v.x);
            __nv_bfloat16 h1 = __float2bfloat16(v.y);
            __nv_bfloat16 l0 = __float2bfloat16(v.x - __bfloat162float(h0));
            __nv_bfloat16 l1 = __float2bfloat16(v.y - __bfloat162float(h1));
            *(uint32_t*)&sAhi[row * PK + k] = pack_bf2(h0, h1);
            *(uint32_t*)&sAlo[row * PK + k] = pack_bf2(l0, l1);
        }
        for (int idx = t; idx < 128 * (KDIM / 8); idx += 256) {
            int n  = idx / (KDIM / 8);
            int kc = (idx % (KDIM / 8)) * 8;
            *(float4*)&sB[n * PK + kc] = *(const float4*)&gBhi[n * KDIM + kc];
        }
        __syncthreads();

        float c[4][4][4];
#pragma unroll
        for (int mi = 0; mi < 4; mi++)
#pragma unroll
            for (int ni = 0; ni < 4; ni++)
#pragma unroll
                for (int q = 0; q < 4; q++) c[mi][ni][q] = 0.f;

        // ---- passes 1 & 2: Ah*Bh, Al*Bh ----
#pragma unroll
        for (int p = 0; p < 2; p++) {
            const __nv_bfloat16* A = (p == 1) ? sAlo : sAhi;
#pragma unroll
            for (int ks = 0; ks < KDIM / 16; ks++) {
                uint32_t a[4][4], b[4][2];
#pragma unroll
                for (int mi = 0; mi < 4; mi++)
                    ldsm_x4(a[mi], smem_u32(&A[(arow + mi * 16) * PK + ks * 16 + ak]));
#pragma unroll
                for (int ni = 0; ni < 4; ni++)
                    ldsm_x2(b[ni], smem_u32(&sB[(brow + ni * 8) * PK + ks * 16 + bk]));
#pragma unroll
                for (int mi = 0; mi < 4; mi++)
#pragma unroll
                    for (int ni = 0; ni < 4; ni++)
                        mma_bf16(c[mi][ni], a[mi], b[ni]);
            }
        }
        __syncthreads();
        // ---- swap B -> Blo ----
        for (int idx = t; idx < 128 * (KDIM / 8); idx += 256) {
            int n  = idx / (KDIM / 8);
            int kc = (idx % (KDIM / 8)) * 8;
            *(float4*)&sB[n * PK + kc] = *(const float4*)&gBlo[n * KDIM + kc];
        }
        __syncthreads();
        // ---- pass 3: Ah*Bl ----
#pragma unroll
        for (int ks = 0; ks < KDIM / 16; ks++) {
            uint32_t a[4][4], b[4][2];
#pragma unroll
            for (int mi = 0; mi < 4; mi++)
                ldsm_x4(a[mi], smem_u32(&sAhi[(arow + mi * 16) * PK + ks * 16 + ak]));
#pragma unroll
            for (int ni = 0; ni < 4; ni++)
                ldsm_x2(b[ni], smem_u32(&sB[(brow + ni * 8) * PK + ks * 16 + bk]));
#pragma unroll
            for (int mi = 0; mi < 4; mi++)
#pragma unroll
                for (int ni = 0; ni < 4; ni++)
                    mma_bf16(c[mi][ni], a[mi], b[ni]);
        }
        __syncthreads();

        if (MODE == 0) {
            const int head = wid >> 1;
#pragma unroll
            for (int mi = 0; mi < 4; mi++) {
                const int row0 = r0 + mbase + mi * 16 + gr;
                float psA = 0.f, pdA = 0.f, psB = 0.f, pdB = 0.f;
#pragma unroll
                for (int ni = 0; ni < 4; ni++) {
                    const int gcol = nbase + ni * 8 + qc;
                    float* cc = c[mi][ni];
                    *(__half2*)&H[(size_t)row0 * HID + gcol] =
                        __floats2half2_rn(cc[0], cc[1]);
                    *(__half2*)&H[(size_t)(row0 + 8) * HID + gcol] =
                        __floats2half2_rn(cc[2], cc[3]);
                    psA = fmaf(cc[0], scr[gcol], fmaf(cc[1], scr[gcol + 1], psA));
                    pdA = fmaf(cc[0], scr[128 + gcol], fmaf(cc[1], scr[128 + gcol + 1], pdA));
                    psB = fmaf(cc[2], scr[gcol], fmaf(cc[3], scr[gcol + 1], psB));
                    pdB = fmaf(cc[2], scr[128 + gcol], fmaf(cc[3], scr[128 + gcol + 1], pdB));
                }
                psA += __shfl_xor_sync(FULLM, psA, 1); psA += __shfl_xor_sync(FULLM, psA, 2);
                pdA += __shfl_xor_sync(FULLM, pdA, 1); pdA += __shfl_xor_sync(FULLM, pdA, 2);
                psB += __shfl_xor_sync(FULLM, psB, 1); psB += __shfl_xor_sync(FULLM, psB, 2);
                pdB += __shfl_xor_sync(FULLM, pdB, 1); pdB += __shfl_xor_sync(FULLM, pdB, 2);
                if ((lane & 3) == 0) {
                    ALS[(size_t)row0 * HEADS + head] = psA;
                    ALD[(size_t)row0 * HEADS + head] = pdA;
                    ALS[(size_t)(row0 + 8) * HEADS + head] = psB;
                    ALD[(size_t)(row0 + 8) * HEADS + head] = pdB;
                }
            }
        } else {
            constexpr int PT = 132;
            float* T = (float*)smem;    // 67.6KB fits in sAhi+sAlo (69.6KB)
#pragma unroll
            for (int mi = 0; mi < 4; mi++) {
                const int rl = mbase + mi * 16 + gr;
#pragma unroll
                for (int ni = 0; ni < 4; ni++) {
                    const int gcol = nbase + ni * 8 + qc;
                    float* cc = c[mi][ni];
                    float t0 = tanh_fast(cc[0] + scr[gcol]);
                    float t1 = tanh_fast(cc[1] + scr[gcol + 1]);
                    float t2 = tanh_fast(cc[2] + scr[gcol]);
                    float t3 = tanh_fast(cc[3] + scr[gcol + 1]);
                    *(float2*)&T[rl * PT + gcol] = make_float2(t0, t1);
                    *(float2*)&T[(rl + 8) * PT + gcol] = make_float2(t2, t3);
                }
            }
            __syncthreads();
            {
                const int row  = t >> 1;
                const int half = t & 1;
                float acc[8];
#pragma unroll
                for (int o = 0; o < 8; o++) acc[o] = 0.f;
                const float* Tr = T + row * PT + half * 64;
                const float* W2s = scr + 128;
#pragma unroll 4
                for (int k = 0; k < 64; k++) {
                    float tv = Tr[k];
                    const float* w = W2s + (half * 64 + k) * 8;
                    float4 wa = *(const float4*)w;
                    float4 wb = *(const float4*)(w + 4);
                    acc[0] = fmaf(tv, wa.x, acc[0]); acc[1] = fmaf(tv, wa.y, acc[1]);
                    acc[2] = fmaf(tv, wa.z, acc[2]); acc[3] = fmaf(tv, wa.w, acc[3]);
                    acc[4] = fmaf(tv, wb.x, acc[4]); acc[5] = fmaf(tv, wb.y, acc[5]);
                    acc[6] = fmaf(tv, wb.z, acc[6]); acc[7] = fmaf(tv, wb.w, acc[7]);
                }
#pragma unroll
                for (int o = 0; o < 8; o++) acc[o] += __shfl_xor_sync(FULLM, acc[o], 1);
                if (half == 0) {
                    float4 oa = make_float4(acc[0] + bm2[0], acc[1] + bm2[1],
                                            acc[2] + bm2[2], acc[3] + bm2[3]);
                    float4 ob = make_float4(acc[4] + bm2[4], acc[5] + bm2[5],
                                            acc[6] + bm2[6], acc[7] + bm2[7]);
                    *(float4*)&OUT[(size_t)(r0 + row) * DOUT + 0] = oa;
                    *(float4*)&OUT[(size_t)(r0 + row) * DOUT + 4] = ob;
                }
            }
        }
        __syncthreads();
    }
}

// =====================================================================
// GAT aggregate — warp-per-node, uint8 adjacency, fp16 H gathers.
// =====================================================================
__global__ __launch_bounds__(256) void gat_aggregate(
    const __half* __restrict__ H, const float* __restrict__ ALS,
    const float* __restrict__ ALD,
    const float* __restrict__ bias, float* __restrict__ Xout)
{
    const int j    = (blockIdx.x * blockDim.x + threadIdx.x) >> 5;
    const int lane = threadIdx.x & 31;
    const int base = (j >> 8) << 8;

    const int d = g_rdeg[j];
    const uint8_t* adj = g_adj8 + (size_t)j * CAP;
    int n0 = (lane < d)      ? base + (int)adj[lane]      : -1;
    int n1 = (lane + 32 < d) ? base + (int)adj[lane + 32] : -1;

    const float4 aldj = *(const float4*)&ALD[(size_t)j * HEADS];

    float e00 = -3.0e38f, e01 = -3.0e38f, e02 = -3.0e38f, e03 = -3.0e38f;
    float e10 = -3.0e38f, e11 = -3.0e38f, e12 = -3.0e38f, e13 = -3.0e38f;
    if (n0 >= 0) {
        float4 s = *(const float4*)&ALS[(size_t)n0 * HEADS];
        e00 = lrelu(s.x + aldj.x); e01 = lrelu(s.y + aldj.y);
        e02 = lrelu(s.z + aldj.z); e03 = lrelu(s.w + aldj.w);
    }
    if (n1 >= 0) {
        float4 s = *(const float4*)&ALS[(size_t)n1 * HEADS];
        e10 = lrelu(s.x + aldj.x); e11 = lrelu(s.y + aldj.y);
        e12 = lrelu(s.z + aldj.z); e13 = lrelu(s.w + aldj.w);
    }

    float a00, a01, a02, a03, a10, a11, a12, a13;
#define SOFTMAX_HEAD(E0, E1, A0, A1)                                        \
    {                                                                       \
        float m = fmaxf(E0, E1);                                            \
        for (int o = 16; o; o >>= 1) m = fmaxf(m, __shfl_xor_sync(FULLM, m, o)); \
        float p0 = (n0 >= 0) ? __expf(E0 - m) : 0.f;                        \
        float p1 = (n1 >= 0) ? __expf(E1 - m) : 0.f;                        \
        float s = p0 + p1;                                                  \
        for (int o = 16; o; o >>= 1) s += __shfl_xor_sync(FULLM, s, o);     \
        float inv = 1.f / (s + 1e-16f);                                     \
        A0 = p0 * inv; A1 = p1 * inv;                                       \
    }
    SOFTMAX_HEAD(e00, e10, a00, a10)
    SOFTMAX_HEAD(e01, e11, a01, a11)
    SOFTMAX_HEAD(e02, e12, a02, a12)
    SOFTMAX_HEAD(e03, e13, a03, a13)
#undef SOFTMAX_HEAD

    float acc0 = 0.f, acc1 = 0.f, acc2 = 0.f, acc3 = 0.f;
    const int dlo = (d < 32) ? d : 32;
    for (int e = 0; e < dlo; e++) {
        int   i  = __shfl_sync(FULLM, n0,  e);
        float w0 = __shfl_sync(FULLM, a00, e);
        float w1 = __shfl_sync(FULLM, a01, e);
        float w2 = __shfl_sync(FULLM, a02, e);
        float w3 = __shfl_sync(FULLM, a03, e);
        const __half* hp = H + (size_t)i * HID + lane;
        acc0 = fmaf(w0, __half2float(__ldg(hp +  0)), acc0);
        acc1 = fmaf(w1, __half2float(__ldg(hp + 32)), acc1);
        acc2 = fmaf(w2, __half2float(__ldg(hp + 64)), acc2);
        acc3 = fmaf(w3, __half2float(__ldg(hp + 96)), acc3);
    }
    for (int e = 32; e < d; e++) {
        int   i  = __shfl_sync(FULLM, n1,  e - 32);
        float w0 = __shfl_sync(FULLM, a10, e - 32);
        float w1 = __shfl_sync(FULLM, a11, e - 32);
        float w2 = __shfl_sync(FULLM, a12, e - 32);
        float w3 = __shfl_sync(FULLM, a13, e - 32);
        const __half* hp = H + (size_t)i * HID + lane;
        acc0 = fmaf(w0, __half2float(__ldg(hp +  0)), acc0);
        acc1 = fmaf(w1, __half2float(__ldg(hp + 32)), acc1);
        acc2 = fmaf(w2, __half2float(__ldg(hp + 64)), acc2);
        acc3 = fmaf(w3, __half2float(__ldg(hp + 96)), acc3);
    }

    float* xp = Xout + (size_t)j * HID + lane;
    xp[ 0] = fmaxf(acc0 + bias[lane +  0], 0.f);
    xp[32] = fmaxf(acc1 + bias[lane + 32], 0.f);
    xp[64] = fmaxf(acc2 + bias[lane + 64], 0.f);
    xp[96] = fmaxf(acc3 + bias[lane + 96], 0.f);
}

// =====================================================================
// Launcher
// =====================================================================
extern "C" void kernel_launch(void* const* d_in, const int* in_sizes, int n_in,
                              void* d_out, int out_size)
{
    const float* obs    = (const float*)d_in[0];
    const float* W1     = (const float*)d_in[1];
    const float* a1_src = (const float*)d_in[2];
    const float* a1_dst = (const float*)d_in[3];
    const float* b1     = (const float*)d_in[4];
    const float* W2     = (const float*)d_in[5];
    const float* a2_src = (const float*)d_in[6];
    const float* a2_dst = (const float*)d_in[7];
    const float* b2     = (const float*)d_in[8];
    const float* Wm1    = (const float*)d_in[9];
    const float* bm1    = (const float*)d_in[10];
    const float* Wm2    = (const float*)d_in[11];
    const float* bm2    = (const float*)d_in[12];
    float* out = (float*)d_out;

    __half* hbuf; cudaGetSymbolAddress((void**)&hbuf, g_hbuf);
    float* xbuf; cudaGetSymbolAddress((void**)&xbuf, g_xbuf);
    float* als;  cudaGetSymbolAddress((void**)&als,  g_als);
    float* ald;  cudaGetSymbolAddress((void**)&ald,  g_ald);
    __nv_bfloat16 *w1h, *w1l, *w2h, *w2l, *wm1h, *wm1l;
    cudaGetSymbolAddress((void**)&w1h,  g_w1_hi);
    cudaGetSymbolAddress((void**)&w1l,  g_w1_lo);
    cudaGetSymbolAddress((void**)&w2h,  g_w2_hi);
    cudaGetSymbolAddress((void**)&w2l,  g_w2_lo);
    cudaGetSymbolAddress((void**)&wm1h, g_wm1_hi);
    cudaGetSymbolAddress((void**)&wm1l, g_wm1_lo);

    // 3 tiles + 4608B scr
    const int SMEM32  = 3 * 128 * (DIN + 8) * 2 + 4608;    //  35,328 B
    const int SMEM128 = 3 * 128 * (HID + 8) * 2 + 4608;    // 109,056 B
    cudaFuncSetAttribute(mma_gemm<DIN, 0>, cudaFuncAttributeMaxDynamicSharedMemorySize, SMEM32);
    cudaFuncSetAttribute(mma_gemm<HID, 0>, cudaFuncAttributeMaxDynamicSharedMemorySize, SMEM128);
    cudaFuncSetAttribute(mma_gemm<HID, 1>, cudaFuncAttributeMaxDynamicSharedMemorySize, SMEM128);

    const int NSM      = 148;
    const int GRID32   = 2 * NSM;
    const int GRID128  = 2 * NSM;   // 2 CTAs/SM now fit (109KB x2 <= 227KB)
    const int AGG_BLOCKS = NODES / 8;

    prep_w_kernel<<<(DIN * 128 + 255) / 256, 256>>>(W1,  DIN, w1h,  w1l);
    prep_w_kernel<<<(HID * 128 + 255) / 256, 256>>>(W2,  HID, w2h,  w2l);
    prep_w_kernel<<<(HID * 128 + 255) / 256, 256>>>(Wm1, HID, wm1h, wm1l);

    knn_kernel<<<Bsz, 512>>>(obs);

    mma_gemm<DIN, 0><<<GRID32, 256, SMEM32>>>(obs, w1h, w1l, a1_src, a1_dst,
        nullptr, nullptr, nullptr, hbuf, als, ald, nullptr);
    gat_aggregate<<<AGG_BLOCKS, 256>>>(hbuf, als, ald, b1, xbuf);

    mma_gemm<HID, 0><<<GRID128, 256, SMEM128>>>(xbuf, w2h, w2l, a2_src, a2_dst,
        nullptr, nullptr, nullptr, hbuf, als, ald, nullptr);
    gat_aggregate<<<AGG_BLOCKS, 256>>>(hbuf, als, ald, b2, xbuf);

    mma_gemm<HID, 1><<<GRID128, 256, SMEM128>>>(xbuf, wm1h, wm1l, nullptr, nullptr,
        bm1, Wm2, bm2, nullptr, nullptr, nullptr, out);
}

// round 14
// speedup vs baseline: 1.5473x; 1.1094x over previous
#include <cuda_runtime.h>
#include <cuda_bf16.h>
#include <cuda_fp16.h>
#include <cstdint>
#include <math.h>

#define Bsz   512
#define Nn    256
#define NODES (Bsz * Nn)      // 131072
#define DIN   32
#define HID   128
#define HEADS 4
#define Knn   5
#define DOUT  8
#define CAP   40
#define NEG_SLOPE 0.2f
#define FULLM 0xffffffffu
#define NTILES (NODES / 128)  // 1024

// ---------------- static device scratch ----------------
__device__ int     g_rdeg[NODES];
__device__ uint8_t g_adj8[(size_t)NODES * CAP];     // local (in-batch) indices
__device__ __half  g_hbuf[(size_t)NODES * HID];     // fp16 H (gathered by aggregate)
__device__ float   g_xbuf[(size_t)NODES * HID];
__device__ float   g_als[(size_t)NODES * HEADS];
__device__ float   g_ald[(size_t)NODES * HEADS];
// bf16 hi/lo images of W^T: [n=128 rows][k] row-major
__device__ __nv_bfloat16 g_w1_hi[128 * DIN],  g_w1_lo[128 * DIN];
__device__ __nv_bfloat16 g_w2_hi[128 * HID],  g_w2_lo[128 * HID];
__device__ __nv_bfloat16 g_wm1_hi[128 * HID], g_wm1_lo[128 * HID];

__device__ __forceinline__ float tanh_fast(float x) {
    return __fdividef(2.f, 1.f + __expf(-2.f * x)) - 1.f;
}
__device__ __forceinline__ float lrelu(float v) {
    return (v > 0.f) ? v : NEG_SLOPE * v;
}
__device__ __forceinline__ uint32_t smem_u32(const void* p) {
    uint32_t a;
    asm("{ .reg .u64 t; cvta.to.shared.u64 t, %1; cvt.u32.u64 %0, t; }" : "=r"(a) : "l"(p));
    return a;
}
__device__ __forceinline__ void ldsm_x4(uint32_t* r, uint32_t addr) {
    asm volatile("ldmatrix.sync.aligned.m8n8.x4.shared.b16 {%0,%1,%2,%3}, [%4];"
                 : "=r"(r[0]), "=r"(r[1]), "=r"(r[2]), "=r"(r[3]) : "r"(addr));
}
__device__ __forceinline__ void ldsm_x2(uint32_t* r, uint32_t addr) {
    asm volatile("ldmatrix.sync.aligned.m8n8.x2.shared.b16 {%0,%1}, [%2];"
                 : "=r"(r[0]), "=r"(r[1]) : "r"(addr));
}
__device__ __forceinline__ void mma_bf16(float* c, const uint32_t* a, const uint32_t* b) {
    asm volatile("mma.sync.aligned.m16n8k16.row.col.f32.bf16.bf16.f32 "
                 "{%0,%1,%2,%3}, {%4,%5,%6,%7}, {%8,%9}, {%0,%1,%2,%3};"
                 : "+f"(c[0]), "+f"(c[1]), "+f"(c[2]), "+f"(c[3])
                 : "r"(a[0]), "r"(a[1]), "r"(a[2]), "r"(a[3]), "r"(b[0]), "r"(b[1]));
}
__device__ __forceinline__ uint32_t pack_bf2(__nv_bfloat16 a, __nv_bfloat16 b) {
    return (uint32_t)__bfloat16_as_ushort(a) | ((uint32_t)__bfloat16_as_ushort(b) << 16);
}

// =====================================================================
// Prep: W [K,128] -> hi/lo bf16 images of W^T [128][K]
// =====================================================================
__global__ void prep_w_kernel(const float* __restrict__ W, int K,
                              __nv_bfloat16* __restrict__ hi, __nv_bfloat16* __restrict__ lo)
{
    int idx = blockIdx.x * blockDim.x + threadIdx.x;
    if (idx >= K * 128) return;
    int k = idx >> 7, n = idx & 127;
    float x = W[idx];
    __nv_bfloat16 h = __float2bfloat16(x);
    __nv_bfloat16 l = __float2bfloat16(x - __bfloat162float(h));
    hi[n * K + k] = h;
    lo[n * K + k] = l;
}

// =====================================================================
// KNN v3: packed float2 coords (1 LDS.64 per candidate).
// =====================================================================
__global__ __launch_bounds__(512) void knn_kernel(const float* __restrict__ obs)
{
    __shared__ float2  sxy[Nn];
    __shared__ int     sdeg[Nn];
    __shared__ uint8_t sadj[Nn * CAP];
    __shared__ float   mbd[Nn * 2 * Knn];
    __shared__ int     mbi[Nn * 2 * Knn];

    const int b = blockIdx.x;
    const int t = threadIdx.x;
    const int n = t & (Nn - 1);
    const int half = t >> 8;

    if (t < Nn) {
        const size_t base = ((size_t)b * Nn + n) * DIN;
        sxy[n] = make_float2(obs[base + 0], obs[base + 1]);
        sdeg[n] = 1;
        sadj[n * CAP + 0] = (uint8_t)n;
    }
    __syncthreads();

    const float2 p = sxy[n];
    float bd[Knn];
    int   bi[Knn];
#pragma unroll
    for (int s = 0; s < Knn; s++) { bd[s] = 3.0e38f; bi[s] = -1; }

    const int j0 = half * 128;
    for (int jj = 0; jj < 128; jj++) {
        const int j = j0 + jj;
        float2 q = sxy[j];
        float dx = q.x - p.x;
        float dy = q.y - p.y;
        float d  = fmaf(dx, dx, dy * dy);
        if (j == n) d = 3.0e38f;
        if (d < bd[Knn - 1]) {
            bd[Knn - 1] = d; bi[Knn - 1] = j;
#pragma unroll
            for (int s = Knn - 2; s >= 0; s--) {
                if (bd[s + 1] < bd[s]) {
                    float td = bd[s]; bd[s] = bd[s + 1]; bd[s + 1] = td;
                    int   ti = bi[s]; bi[s] = bi[s + 1]; bi[s + 1] = ti;
                }
            }
        }
    }
#pragma unroll
    for (int s = 0; s < Knn; s++) {
        mbd[(n * 2 + half) * Knn + s] = bd[s];
        mbi[(n * 2 + half) * Knn + s] = bi[s];
    }
    __syncthreads();

    if (t < Nn) {
        const float* A  = &mbd[(n * 2 + 0) * Knn];
        const float* B  = &mbd[(n * 2 + 1) * Knn];
        const int*   Ai = &mbi[(n * 2 + 0) * Knn];
        const int*   Bi = &mbi[(n * 2 + 1) * Knn];
        int ia = 0, ib = 0;
#pragma unroll
        for (int s = 0; s < Knn; s++) {
            int jn;
            if (A[ia] <= B[ib]) jn = Ai[ia++];
            else                jn = Bi[ib++];
            int p2 = atomicAdd(&sdeg[jn], 1);
            if (p2 < CAP) sadj[jn * CAP + p2] = (uint8_t)n;
        }
    }
    __syncthreads();

    if (t < Nn) {
        int deg = min(sdeg[n], CAP);
        g_rdeg[b * Nn + n] = deg;
        uint8_t* dst = g_adj8 + (size_t)(b * Nn + n) * CAP;
        const uint32_t* srcw = (const uint32_t*)&sadj[n * CAP];
#pragma unroll
        for (int w = 0; w < CAP / 4; w++)
            ((uint32_t*)dst)[w] = srcw[w];
    }
}

// =====================================================================
// PERSISTENT mma.sync GEMM, 3-tile smem, 2 CTAs/SM (unchanged, measured).
// =====================================================================
template<int KDIM, int MODE>
__global__ __launch_bounds__(256, 2) void mma_gemm(
    const float* __restrict__ X,
    const __nv_bfloat16* __restrict__ gBhi, const __nv_bfloat16* __restrict__ gBlo,
    const float* __restrict__ asrc, const float* __restrict__ adst,
    const float* __restrict__ bias, const float* __restrict__ Wm2,
    const float* __restrict__ bm2,
    __half* __restrict__ H, float* __restrict__ ALS, float* __restrict__ ALD,
    float* __restrict__ OUT)
{
    constexpr int PK = KDIM + 8;
    extern __shared__ __align__(16) char smem[];
    __nv_bfloat16* sAhi = (__nv_bfloat16*)smem;
    __nv_bfloat16* sAlo = sAhi + 128 * PK;
    __nv_bfloat16* sB   = sAlo + 128 * PK;
    float* scr = (float*)(sB + 128 * PK);

    const int t = threadIdx.x, wid = t >> 5, lane = t & 31;

    if (MODE == 0) {
        if (t < 128) { scr[t] = asrc[t]; scr[128 + t] = adst[t]; }
    } else {
        if (t < 128) scr[t] = bias[t];
        for (int e = t; e < 1024; e += 256) scr[128 + e] = Wm2[e];
    }
    __syncthreads();

    const int mbase = (wid & 1) * 64;
    const int nbase = (wid >> 1) * 32;
    const int arow = mbase + (lane & 7) + ((lane >> 3) & 1) * 8;
    const int ak   = (lane >> 4) * 8;
    const int brow = nbase + (lane & 7);
    const int bk   = ((lane >> 3) & 1) * 8;
    const int gr = lane >> 2;
    const int qc = (lane & 3) * 2;

    for (int tile = blockIdx.x; tile < NTILES; tile += gridDim.x) {
        const int r0 = tile * 128;

        for (int idx = t; idx < 128 * (KDIM / 2); idx += 256) {
            int row = idx / (KDIM / 2);
            int k   = (idx % (KDIM / 2)) * 2;
            float2 v = *(const float2*)&X[(size_t)(r0 + row) * KDIM + k];
            __nv_bfloat16 h0 = __float2bfloat16(v.x);
            __nv_bfloat16 h1 = __float2bfloat16(v.y);
            __nv_bfloat16 l0 = __float2bfloat16(v.x - __bfloat162float(h0));
            __nv_bfloat16 l1 = __float2bfloat16(v.y - __bfloat162float(h1));
            *(uint32_t*)&sAhi[row * PK + k] = pack_bf2(h0, h1);
            *(uint32_t*)&sAlo[row * PK + k] = pack_bf2(l0, l1);
        }
        for (int idx = t; idx < 128 * (KDIM / 8); idx += 256) {
            int n  = idx / (KDIM / 8);
            int kc = (idx % (KDIM / 8)) * 8;
            *(float4*)&sB[n * PK + kc] = *(const float4*)&gBhi[n * KDIM + kc];
        }
        __syncthreads();

        float c[4][4][4];
#pragma unroll
        for (int mi = 0; mi < 4; mi++)
#pragma unroll
            for (int ni = 0; ni < 4; ni++)
#pragma unroll
                for (int q = 0; q < 4; q++) c[mi][ni][q] = 0.f;

#pragma unroll
        for (int p = 0; p < 2; p++) {
            const __nv_bfloat16* A = (p == 1) ? sAlo : sAhi;
#pragma unroll
            for (int ks = 0; ks < KDIM / 16; ks++) {
                uint32_t a[4][4], b[4][2];
#pragma unroll
                for (int mi = 0; mi < 4; mi++)
                    ldsm_x4(a[mi], smem_u32(&A[(arow + mi * 16) * PK + ks * 16 + ak]));
#pragma unroll
                for (int ni = 0; ni < 4; ni++)
                    ldsm_x2(b[ni], smem_u32(&sB[(brow + ni * 8) * PK + ks * 16 + bk]));
#pragma unroll
                for (int mi = 0; mi < 4; mi++)
#pragma unroll
                    for (int ni = 0; ni < 4; ni++)
                        mma_bf16(c[mi][ni], a[mi], b[ni]);
            }
        }
        __syncthreads();
        for (int idx = t; idx < 128 * (KDIM / 8); idx += 256) {
            int n  = idx / (KDIM / 8);
            int kc = (idx % (KDIM / 8)) * 8;
            *(float4*)&sB[n * PK + kc] = *(const float4*)&gBlo[n * KDIM + kc];
        }
        __syncthreads();
#pragma unroll
        for (int ks = 0; ks < KDIM / 16; ks++) {
            uint32_t a[4][4], b[4][2];
#pragma unroll
            for (int mi = 0; mi < 4; mi++)
                ldsm_x4(a[mi], smem_u32(&sAhi[(arow + mi * 16) * PK + ks * 16 + ak]));
#pragma unroll
            for (int ni = 0; ni < 4; ni++)
                ldsm_x2(b[ni], smem_u32(&sB[(brow + ni * 8) * PK + ks * 16 + bk]));
#pragma unroll
            for (int mi = 0; mi < 4; mi++)
#pragma unroll
                for (int ni = 0; ni < 4; ni++)
                    mma_bf16(c[mi][ni], a[mi], b[ni]);
        }
        __syncthreads();

        if (MODE == 0) {
            const int head = wid >> 1;
#pragma unroll
            for (int mi = 0; mi < 4; mi++) {
                const int row0 = r0 + mbase + mi * 16 + gr;
                float psA = 0.f, pdA = 0.f, psB = 0.f, pdB = 0.f;
#pragma unroll
                for (int ni = 0; ni < 4; ni++) {
                    const int gcol = nbase + ni * 8 + qc;
                    float* cc = c[mi][ni];
                    *(__half2*)&H[(size_t)row0 * HID + gcol] =
                        __floats2half2_rn(cc[0], cc[1]);
                    *(__half2*)&H[(size_t)(row0 + 8) * HID + gcol] =
                        __floats2half2_rn(cc[2], cc[3]);
                    psA = fmaf(cc[0], scr[gcol], fmaf(cc[1], scr[gcol + 1], psA));
                    pdA = fmaf(cc[0], scr[128 + gcol], fmaf(cc[1], scr[128 + gcol + 1], pdA));
                    psB = fmaf(cc[2], scr[gcol], fmaf(cc[3], scr[gcol + 1], psB));
                    pdB = fmaf(cc[2], scr[128 + gcol], fmaf(cc[3], scr[128 + gcol + 1], pdB));
                }
                psA += __shfl_xor_sync(FULLM, psA, 1); psA += __shfl_xor_sync(FULLM, psA, 2);
                pdA += __shfl_xor_sync(FULLM, pdA, 1); pdA += __shfl_xor_sync(FULLM, pdA, 2);
                psB += __shfl_xor_sync(FULLM, psB, 1); psB += __shfl_xor_sync(FULLM, psB, 2);
                pdB += __shfl_xor_sync(FULLM, pdB, 1); pdB += __shfl_xor_sync(FULLM, pdB, 2);
                if ((lane & 3) == 0) {
                    ALS[(size_t)row0 * HEADS + head] = psA;
                    ALD[(size_t)row0 * HEADS + head] = pdA;
                    ALS[(size_t)(row0 + 8) * HEADS + head] = psB;
                    ALD[(size_t)(row0 + 8) * HEADS + head] = pdB;
                }
            }
        } else {
            constexpr int PT = 132;
            float* T = (float*)smem;
#pragma unroll
            for (int mi = 0; mi < 4; mi++) {
                const int rl = mbase + mi * 16 + gr;
#pragma unroll
                for (int ni = 0; ni < 4; ni++) {
                    const int gcol = nbase + ni * 8 + qc;
                    float* cc = c[mi][ni];
                    float t0 = tanh_fast(cc[0] + scr[gcol]);
                    float t1 = tanh_fast(cc[1] + scr[gcol + 1]);
                    float t2 = tanh_fast(cc[2] + scr[gcol]);
                    float t3 = tanh_fast(cc[3] + scr[gcol + 1]);
                    *(float2*)&T[rl * PT + gcol] = make_float2(t0, t1);
                    *(float2*)&T[(rl + 8) * PT + gcol] = make_float2(t2, t3);
                }
            }
            __syncthreads();
            {
                const int row  = t >> 1;
                const int half = t & 1;
                float acc[8];
#pragma unroll
                for (int o = 0; o < 8; o++) acc[o] = 0.f;
                const float* Tr = T + row * PT + half * 64;
                const float* W2s = scr + 128;
#pragma unroll 4
                for (int k = 0; k < 64; k++) {
                    float tv = Tr[k];
                    const float* w = W2s + (half * 64 + k) * 8;
                    float4 wa = *(const float4*)w;
                    float4 wb = *(const float4*)(w + 4);
                    acc[0] = fmaf(tv, wa.x, acc[0]); acc[1] = fmaf(tv, wa.y, acc[1]);
                    acc[2] = fmaf(tv, wa.z, acc[2]); acc[3] = fmaf(tv, wa.w, acc[3]);
                    acc[4] = fmaf(tv, wb.x, acc[4]); acc[5] = fmaf(tv, wb.y, acc[5]);
                    acc[6] = fmaf(tv, wb.z, acc[6]); acc[7] = fmaf(tv, wb.w, acc[7]);
                }
#pragma unroll
                for (int o = 0; o < 8; o++) acc[o] += __shfl_xor_sync(FULLM, acc[o], 1);
                if (half == 0) {
                    float4 oa = make_float4(acc[0] + bm2[0], acc[1] + bm2[1],
                                            acc[2] + bm2[2], acc[3] + bm2[3]);
                    float4 ob = make_float4(acc[4] + bm2[4], acc[5] + bm2[5],
                                            acc[6] + bm2[6], acc[7] + bm2[7]);
                    *(float4*)&OUT[(size_t)(r0 + row) * DOUT + 0] = oa;
                    *(float4*)&OUT[(size_t)(r0 + row) * DOUT + 4] = ob;
                }
            }
        }
        __syncthreads();
    }
}

// =====================================================================
// GAT aggregate v3: warp-per-node; softmax as before, then alphas+indices
// parked in smem; d-loop = 2 LDS + 1 uint2 LDG + 4 FMA, zero shuffles.
// Lane owns 4 consecutive H cols (single head). Coalesced float4 output.
// =====================================================================
__global__ __launch_bounds__(256) void gat_aggregate(
    const __half* __restrict__ H, const float* __restrict__ ALS,
    const float* __restrict__ ALD,
    const float* __restrict__ bias, float* __restrict__ Xout)
{
    __shared__ int   s_idx[8][64];
    __shared__ float s_alp[8][64 * 4];

    const int warp = threadIdx.x >> 5;
    const int j    = (blockIdx.x * blockDim.x + threadIdx.x) >> 5;
    const int lane = threadIdx.x & 31;
    const int base = (j >> 8) << 8;

    const int d = g_rdeg[j];
    const uint8_t* adj = g_adj8 + (size_t)j * CAP;
    int n0 = (lane < d)      ? base + (int)adj[lane]      : -1;
    int n1 = (lane + 32 < d) ? base + (int)adj[lane + 32] : -1;

    const float4 aldj = *(const float4*)&ALD[(size_t)j * HEADS];

    float e00 = -3.0e38f, e01 = -3.0e38f, e02 = -3.0e38f, e03 = -3.0e38f;
    float e10 = -3.0e38f, e11 = -3.0e38f, e12 = -3.0e38f, e13 = -3.0e38f;
    if (n0 >= 0) {
        float4 s = *(const float4*)&ALS[(size_t)n0 * HEADS];
        e00 = lrelu(s.x + aldj.x); e01 = lrelu(s.y + aldj.y);
        e02 = lrelu(s.z + aldj.z); e03 = lrelu(s.w + aldj.w);
    }
    if (n1 >= 0) {
        float4 s = *(const float4*)&ALS[(size_t)n1 * HEADS];
        e10 = lrelu(s.x + aldj.x); e11 = lrelu(s.y + aldj.y);
        e12 = lrelu(s.z + aldj.z); e13 = lrelu(s.w + aldj.w);
    }

    float a00, a01, a02, a03, a10, a11, a12, a13;
#define SOFTMAX_HEAD(E0, E1, A0, A1)                                        \
    {                                                                       \
        float m = fmaxf(E0, E1);                                            \
        for (int o = 16; o; o >>= 1) m = fmaxf(m, __shfl_xor_sync(FULLM, m, o)); \
        float p0 = (n0 >= 0) ? __expf(E0 - m) : 0.f;                        \
        float p1 = (n1 >= 0) ? __expf(E1 - m) : 0.f;                        \
        float s = p0 + p1;                                                  \
        for (int o = 16; o; o >>= 1) s += __shfl_xor_sync(FULLM, s, o);     \
        float inv = 1.f / (s + 1e-16f);                                     \
        A0 = p0 * inv; A1 = p1 * inv;                                       \
    }
    SOFTMAX_HEAD(e00, e10, a00, a10)
    SOFTMAX_HEAD(e01, e11, a01, a11)
    SOFTMAX_HEAD(e02, e12, a02, a12)
    SOFTMAX_HEAD(e03, e13, a03, a13)
#undef SOFTMAX_HEAD

    s_idx[warp][lane]      = n0;
    s_idx[warp][lane + 32] = n1;
    *(float4*)&s_alp[warp][lane * 4]        = make_float4(a00, a01, a02, a03);
    *(float4*)&s_alp[warp][(lane + 32) * 4] = make_float4(a10, a11, a12, a13);
    __syncwarp();

    const int hsel = lane >> 3;          // head of this lane's 4 columns
    const int coff = lane * 4;           // column offset
    float ax = 0.f, ay = 0.f, az = 0.f, aw = 0.f;
    for (int e = 0; e < d; e++) {
        int   i = s_idx[warp][e];
        float w = s_alp[warp][e * 4 + hsel];
        uint2 hv = *(const uint2*)&H[(size_t)i * HID + coff];
        float2 f0 = __half22float2(*(__half2*)&hv.x);
        float2 f1 = __half22float2(*(__half2*)&hv.y);
        ax = fmaf(w, f0.x, ax);
        ay = fmaf(w, f0.y, ay);
        az = fmaf(w, f1.x, az);
        aw = fmaf(w, f1.y, aw);
    }

    float4 bv = *(const float4*)&bias[coff];
    float4 o = make_float4(fmaxf(ax + bv.x, 0.f), fmaxf(ay + bv.y, 0.f),
                           fmaxf(az + bv.z, 0.f), fmaxf(aw + bv.w, 0.f));
    *(float4*)&Xout[(size_t)j * HID + coff] = o;
}

// =====================================================================
// Launcher
// =====================================================================
extern "C" void kernel_launch(void* const* d_in, const int* in_sizes, int n_in,
                              void* d_out, int out_size)
{
    const float* obs    = (const float*)d_in[0];
    const float* W1     = (const float*)d_in[1];
    const float* a1_src = (const float*)d_in[2];
    const float* a1_dst = (const float*)d_in[3];
    const float* b1     = (const float*)d_in[4];
    const float* W2     = (const float*)d_in[5];
    const float* a2_src = (const float*)d_in[6];
    const float* a2_dst = (const float*)d_in[7];
    const float* b2     = (const float*)d_in[8];
    const float* Wm1    = (const float*)d_in[9];
    const float* bm1    = (const float*)d_in[10];
    const float* Wm2    = (const float*)d_in[11];
    const float* bm2    = (const float*)d_in[12];
    float* out = (float*)d_out;

    __half* hbuf; cudaGetSymbolAddress((void**)&hbuf, g_hbuf);
    float* xbuf; cudaGetSymbolAddress((void**)&xbuf, g_xbuf);
    float* als;  cudaGetSymbolAddress((void**)&als,  g_als);
    float* ald;  cudaGetSymbolAddress((void**)&ald,  g_ald);
    __nv_bfloat16 *w1h, *w1l, *w2h, *w2l, *wm1h, *wm1l;
    cudaGetSymbolAddress((void**)&w1h,  g_w1_hi);
    cudaGetSymbolAddress((void**)&w1l,  g_w1_lo);
    cudaGetSymbolAddress((void**)&w2h,  g_w2_hi);
    cudaGetSymbolAddress((void**)&w2l,  g_w2_lo);
    cudaGetSymbolAddress((void**)&wm1h, g_wm1_hi);
    cudaGetSymbolAddress((void**)&wm1l, g_wm1_lo);

    const int SMEM32  = 3 * 128 * (DIN + 8) * 2 + 4608;    //  35,328 B
    const int SMEM128 = 3 * 128 * (HID + 8) * 2 + 4608;    // 109,056 B
    cudaFuncSetAttribute(mma_gemm<DIN, 0>, cudaFuncAttributeMaxDynamicSharedMemorySize, SMEM32);
    cudaFuncSetAttribute(mma_gemm<HID, 0>, cudaFuncAttributeMaxDynamicSharedMemorySize, SMEM128);
    cudaFuncSetAttribute(mma_gemm<HID, 1>, cudaFuncAttributeMaxDynamicSharedMemorySize, SMEM128);

    const int NSM      = 148;
    const int GRID32   = 2 * NSM;
    const int GRID128  = 2 * NSM;
    const int AGG_BLOCKS = NODES / 8;

    prep_w_kernel<<<(DIN * 128 + 255) / 256, 256>>>(W1,  DIN, w1h,  w1l);
    prep_w_kernel<<<(HID * 128 + 255) / 256, 256>>>(W2,  HID, w2h,  w2l);
    prep_w_kernel<<<(HID * 128 + 255) / 256, 256>>>(Wm1, HID, wm1h, wm1l);

    knn_kernel<<<Bsz, 512>>>(obs);

    mma_gemm<DIN, 0><<<GRID32, 256, SMEM32>>>(obs, w1h, w1l, a1_src, a1_dst,
        nullptr, nullptr, nullptr, hbuf, als, ald, nullptr);
    gat_aggregate<<<AGG_BLOCKS, 256>>>(hbuf, als, ald, b1, xbuf);

    mma_gemm<HID, 0><<<GRID128, 256, SMEM128>>>(xbuf, w2h, w2l, a2_src, a2_dst,
        nullptr, nullptr, nullptr, hbuf, als, ald, nullptr);
    gat_aggregate<<<AGG_BLOCKS, 256>>>(hbuf, als, ald, b2, xbuf);

    mma_gemm<HID, 1><<<GRID128, 256, SMEM128>>>(xbuf, wm1h, wm1l, nullptr, nullptr,
        bm1, Wm2, bm2, nullptr, nullptr, nullptr, out);
}